// round 2
// baseline (speedup 1.0000x reference)
#include <cuda_runtime.h>
#include <math.h>

#define NN 100000
#define NE 1600000
#define NG 200
#define HID 64

// ---------------- scratch (static device globals; no allocation) ----------------
__device__ int   g_deg[NN];
__device__ int   g_incl[NN];
__device__ int   g_rowptr[NN + 1];
__device__ int   g_cur[NN];
__device__ int   g_bsums[256];
__device__ int   g_csr[NE];
__device__ float g_hA[NN * HID];
__device__ float g_hB[NN * HID];
__device__ float g_obuf[NG * 196];

__device__ __forceinline__ float silu_f(float z) { return z / (1.f + __expf(-z)); }

// ---------------- CSR build ----------------
__global__ void zero_deg_kernel(int* deg) {
    int i = blockIdx.x * blockDim.x + threadIdx.x;
    if (i < NN) deg[i] = 0;
}

__global__ void hist_kernel(const int* __restrict__ ei, int* __restrict__ deg) {
    int e = blockIdx.x * blockDim.x + threadIdx.x;
    if (e < NE) atomicAdd(&deg[ei[NE + e]], 1);
}

__global__ void scan1_kernel(const int* __restrict__ deg, int* __restrict__ incl,
                             int* __restrict__ bsums) {
    __shared__ int s[1024];
    int tid = threadIdx.x;
    int i = blockIdx.x * 1024 + tid;
    s[tid] = (i < NN) ? deg[i] : 0;
    __syncthreads();
    for (int off = 1; off < 1024; off <<= 1) {
        int v = (tid >= off) ? s[tid - off] : 0;
        __syncthreads();
        s[tid] += v;
        __syncthreads();
    }
    if (i < NN) incl[i] = s[tid];
    if (tid == 1023) bsums[blockIdx.x] = s[1023];
}

__global__ void scan2_kernel(int* bsums, int nb) {
    __shared__ int s[128];
    int tid = threadIdx.x;
    int v = (tid < nb) ? bsums[tid] : 0;
    s[tid] = v;
    __syncthreads();
    for (int off = 1; off < 128; off <<= 1) {
        int t = (tid >= off) ? s[tid - off] : 0;
        __syncthreads();
        s[tid] += t;
        __syncthreads();
    }
    if (tid < nb) bsums[tid] = s[tid] - v;  // exclusive
}

__global__ void scan3_kernel(const int* __restrict__ incl, const int* __restrict__ deg,
                             const int* __restrict__ bsums, int* __restrict__ rowptr,
                             int* __restrict__ cur) {
    int i = blockIdx.x * blockDim.x + threadIdx.x;
    if (i < NN) {
        int val = incl[i] + bsums[i >> 10];
        rowptr[i + 1] = val;
        cur[i] = val - deg[i];
    }
    if (i == 0) rowptr[0] = 0;
}

__global__ void scatter_kernel(const int* __restrict__ ei, int* __restrict__ cur,
                               int* __restrict__ csr) {
    int e = blockIdx.x * blockDim.x + threadIdx.x;
    if (e < NE) {
        int d = ei[NE + e];
        int p = atomicAdd(&cur[d], 1);
        csr[p] = ei[e];
    }
}

// ---------------- layer 0 (IN=4): fully fused sage + LN + x_res + silu ----------------
__global__ __launch_bounds__(256) void layer0_kernel(
    const float* __restrict__ x, const int* __restrict__ rowptr, const int* __restrict__ csr,
    const float* __restrict__ Wl0, const float* __restrict__ bl0, const float* __restrict__ Wr0,
    const float* __restrict__ Wres, const float* __restrict__ bres,
    const float* __restrict__ lng, const float* __restrict__ lnb, float* __restrict__ hout) {
    int tid = threadIdx.x;
    int grp = tid >> 6;
    int l = tid & 63;
    int v = blockIdx.x * 4 + grp;
    bool valid = (v < NN);
    __shared__ float sMx[4][64], sSm[4][64], sAgg[4][8], sX[4][4], sP[4][2][2];
    int start = 0, end = 0;
    if (valid) { start = rowptr[v]; end = rowptr[v + 1]; }
    if (valid && l < 4) sX[grp][l] = x[v * 4 + l];
    int es = l >> 2, dim = l & 3;
    float mx = -INFINITY, sm = 0.f;
    for (int e = start + es; e < end; e += 16) {
        int s = csr[e];
        float val = x[s * 4 + dim];
        mx = fmaxf(mx, val);
        sm += val;
    }
    sMx[grp][l] = mx; sSm[grp][l] = sm;
    __syncthreads();
    if (l < 8) {
        int dd = l & 3;
        int deg = end - start;
        if (l < 4) {
            float m = -INFINITY;
            #pragma unroll
            for (int j = 0; j < 16; j++) m = fmaxf(m, sMx[grp][j * 4 + dd]);
            sAgg[grp][dd] = (deg > 0) ? m : 0.f;
        } else {
            float s2 = 0.f;
            #pragma unroll
            for (int j = 0; j < 16; j++) s2 += sSm[grp][j * 4 + dd];
            sAgg[grp][4 + dd] = s2 / (float)(deg > 0 ? deg : 1);
        }
    }
    __syncthreads();
    float acc = __ldg(bl0 + l);
    #pragma unroll
    for (int k = 0; k < 8; k++) acc += sAgg[grp][k] * __ldg(Wl0 + k * 64 + l);
    float xres = __ldg(bres + l);
    #pragma unroll
    for (int k = 0; k < 4; k++) {
        float xv = sX[grp][k];
        acc += xv * __ldg(Wr0 + k * 64 + l);
        xres += xv * __ldg(Wres + k * 64 + l);
    }
    float s1 = acc, q1 = acc * acc;
    #pragma unroll
    for (int m2 = 1; m2 < 32; m2 <<= 1) {
        s1 += __shfl_xor_sync(0xffffffffu, s1, m2);
        q1 += __shfl_xor_sync(0xffffffffu, q1, m2);
    }
    int w = (tid >> 5) & 1;
    if ((tid & 31) == 0) { sP[grp][w][0] = s1; sP[grp][w][1] = q1; }
    __syncthreads();
    float S = sP[grp][0][0] + sP[grp][1][0];
    float Q = sP[grp][0][1] + sP[grp][1][1];
    float mean = S * (1.f / 64.f);
    float var = Q * (1.f / 64.f) - mean * mean;
    float rstd = rsqrtf(var + 1e-5f);
    float z = (acc - mean) * rstd * __ldg(lng + l) + __ldg(lnb + l) + xres;
    if (valid) hout[v * 64 + l] = silu_f(z);
}

// ---------------- fused hidden sage layer: gather-agg + GEMM(K=192) + LN + res + silu ---
// A-panel per 64-node tile in smem: cols [0:64)=max, [64:128)=mean, [128:192)=own feats.
// sW = [Wl(128x64); Wr(64x64)] contiguous. Persistent blocks, 2 blocks/SM so one
// block's L2-bound gather overlaps the other's FFMA-bound GEMM.
#define SAH_STRIDE 196
#define SG_SMEM ((192 * 64 + 64 * SAH_STRIDE) * 4)
__global__ __launch_bounds__(256) void sage_fused_kernel(
    const float* __restrict__ hin, const int* __restrict__ rowptr, const int* __restrict__ csr,
    const float* __restrict__ Wl, const float* __restrict__ bl, const float* __restrict__ Wr,
    const float* __restrict__ lng, const float* __restrict__ lnb, float* __restrict__ hout) {
    extern __shared__ float smem[];
    float* sW = smem;                  // 192 x 64
    float* sAH = sW + 192 * 64;        // 64 x 196
    int tid = threadIdx.x;
    for (int i = tid; i < 128 * 64 / 4; i += 256) ((float4*)sW)[i] = ((const float4*)Wl)[i];
    for (int i = tid; i < 64 * 64 / 4; i += 256)
        ((float4*)(sW + 128 * 64))[i] = ((const float4*)Wr)[i];
    int grp = tid >> 6;    // gather group 0..3 (64 lanes)
    int l = tid & 63;      // feature lane
    int ty = tid >> 4, tx = tid & 15;  // gemm mapping: 4 rows x 4 cols per thread
    float4 bv = *(const float4*)(bl + tx * 4);
    float4 gv = *(const float4*)(lng + tx * 4);
    float4 lbv = *(const float4*)(lnb + tx * 4);
    const int NT = (NN + 63) >> 6;
    for (int t = blockIdx.x; t < NT; t += gridDim.x) {
        __syncthreads();
        int base = t * 64;
        // own features -> cols 128..191
        for (int i = tid; i < 64 * 16; i += 256) {
            int r = i >> 4, c = i & 15;
            int row = base + r;
            float4 vv = make_float4(0.f, 0.f, 0.f, 0.f);
            if (row < NN) vv = ((const float4*)(hin + (long)row * 64))[c];
            *(float4*)(sAH + r * SAH_STRIDE + 128 + c * 4) = vv;
        }
        // gather-aggregate: group handles nodes base+grp, base+grp+4, ...
        for (int nb = grp; nb < 64; nb += 4) {
            int v = base + nb;
            float mx = -INFINITY, sm = 0.f;
            int deg = 0;
            if (v < NN) {
                int s0 = rowptr[v], e0 = rowptr[v + 1];
                deg = e0 - s0;
                int e = s0;
                for (; e + 8 <= e0; e += 8) {
                    int i0 = csr[e], i1 = csr[e + 1], i2 = csr[e + 2], i3 = csr[e + 3];
                    int i4 = csr[e + 4], i5 = csr[e + 5], i6 = csr[e + 6], i7 = csr[e + 7];
                    float v0 = hin[i0 * 64 + l], v1 = hin[i1 * 64 + l];
                    float v2 = hin[i2 * 64 + l], v3 = hin[i3 * 64 + l];
                    float v4 = hin[i4 * 64 + l], v5 = hin[i5 * 64 + l];
                    float v6 = hin[i6 * 64 + l], v7 = hin[i7 * 64 + l];
                    mx = fmaxf(mx, fmaxf(fmaxf(v0, v1), fmaxf(v2, v3)));
                    mx = fmaxf(mx, fmaxf(fmaxf(v4, v5), fmaxf(v6, v7)));
                    sm += ((v0 + v1) + (v2 + v3)) + ((v4 + v5) + (v6 + v7));
                }
                for (; e < e0; e++) {
                    float vv = hin[csr[e] * 64 + l];
                    mx = fmaxf(mx, vv);
                    sm += vv;
                }
            }
            sAH[nb * SAH_STRIDE + l] = (deg > 0) ? mx : 0.f;
            sAH[nb * SAH_STRIDE + 64 + l] = sm / (float)(deg > 0 ? deg : 1);
        }
        __syncthreads();
        // GEMM: 64x64 out, K=192, float4 k-unroll
        float acc[4][4];
        #pragma unroll
        for (int i = 0; i < 4; i++)
            #pragma unroll
            for (int j = 0; j < 4; j++) acc[i][j] = 0.f;
        #pragma unroll 2
        for (int k = 0; k < 192; k += 4) {
            float4 w0 = *(float4*)(sW + (k + 0) * 64 + tx * 4);
            float4 w1 = *(float4*)(sW + (k + 1) * 64 + tx * 4);
            float4 w2 = *(float4*)(sW + (k + 2) * 64 + tx * 4);
            float4 w3 = *(float4*)(sW + (k + 3) * 64 + tx * 4);
            #pragma unroll
            for (int i = 0; i < 4; i++) {
                float4 a = *(float4*)(sAH + (ty * 4 + i) * SAH_STRIDE + k);
                acc[i][0] += a.x * w0.x; acc[i][1] += a.x * w0.y;
                acc[i][2] += a.x * w0.z; acc[i][3] += a.x * w0.w;
                acc[i][0] += a.y * w1.x; acc[i][1] += a.y * w1.y;
                acc[i][2] += a.y * w1.z; acc[i][3] += a.y * w1.w;
                acc[i][0] += a.z * w2.x; acc[i][1] += a.z * w2.y;
                acc[i][2] += a.z * w2.z; acc[i][3] += a.z * w2.w;
                acc[i][0] += a.w * w3.x; acc[i][1] += a.w * w3.y;
                acc[i][2] += a.w * w3.z; acc[i][3] += a.w * w3.w;
            }
        }
        #pragma unroll
        for (int i = 0; i < 4; i++) {
            float v0 = acc[i][0] + bv.x;
            float v1 = acc[i][1] + bv.y;
            float v2 = acc[i][2] + bv.z;
            float v3 = acc[i][3] + bv.w;
            float s = (v0 + v1) + (v2 + v3);
            float q = v0 * v0 + v1 * v1 + v2 * v2 + v3 * v3;
            #pragma unroll
            for (int m2 = 1; m2 < 16; m2 <<= 1) {
                s += __shfl_xor_sync(0xffffffffu, s, m2);
                q += __shfl_xor_sync(0xffffffffu, q, m2);
            }
            float mean = s * (1.f / 64.f);
            float var = q * (1.f / 64.f) - mean * mean;
            float rstd = rsqrtf(var + 1e-5f);
            int row = ty * 4 + i;
            int grow = base + row;
            if (grow < NN) {
                const float* hr = sAH + row * SAH_STRIDE + 128 + tx * 4;
                float4 o;
                o.x = silu_f((v0 - mean) * rstd * gv.x + lbv.x + hr[0]);
                o.y = silu_f((v1 - mean) * rstd * gv.y + lbv.y + hr[1]);
                o.z = silu_f((v2 - mean) * rstd * gv.z + lbv.z + hr[2]);
                o.w = silu_f((v3 - mean) * rstd * gv.w + lbv.w + hr[3]);
                *(float4*)(hout + (long)grow * 64 + tx * 4) = o;
            }
        }
    }
}

// ---------------- node MLP: silu(h@W1+b1) -> LN -> @W2+b2, fused ----------------
#define MLP_SMEM ((64 * 256 + 256 * 64 + 32 * 68 + 32 * 260 + 128) * 4)
__global__ __launch_bounds__(256) void mlp_kernel(
    const float* __restrict__ hin, const float* __restrict__ W1, const float* __restrict__ b1,
    const float* __restrict__ gg, const float* __restrict__ bn,
    const float* __restrict__ W2, const float* __restrict__ b2, float* __restrict__ hout) {
    extern __shared__ float smem[];
    float* sW1 = smem;               // 64*256
    float* sW2 = sW1 + 64 * 256;     // 256*64
    float* sA = sW2 + 256 * 64;      // 32 x 68
    float* sT = sA + 32 * 68;        // 32 x 260
    float* sRed = sT + 32 * 260;     // 8 warps * 16
    int tid = threadIdx.x;
    for (int i = tid; i < 64 * 256 / 4; i += 256) ((float4*)sW1)[i] = ((const float4*)W1)[i];
    for (int i = tid; i < 256 * 64 / 4; i += 256) ((float4*)sW2)[i] = ((const float4*)W2)[i];
    int ty = tid >> 6, tx = tid & 63;
    int ry = tid >> 4, cx = tid & 15;
    int warp = tid >> 5;
    float4 b1v = *(const float4*)(b1 + tx * 4);
    float4 gv = *(const float4*)(gg + tx * 4);
    float4 bnv = *(const float4*)(bn + tx * 4);
    float4 b2v = *(const float4*)(b2 + cx * 4);
    const int NT = NN / 32;  // 3125 exact
    for (int t = blockIdx.x; t < NT; t += gridDim.x) {
        __syncthreads();
        int base = t * 32;
        for (int i = tid; i < 32 * 16; i += 256) {
            int r = i >> 4, c = i & 15;
            ((float4*)(sA + r * 68))[c] = ((const float4*)(hin + (long)(base + r) * 64))[c];
        }
        __syncthreads();
        float acc[8][4];
        #pragma unroll
        for (int i = 0; i < 8; i++)
            #pragma unroll
            for (int j = 0; j < 4; j++) acc[i][j] = 0.f;
        #pragma unroll 2
        for (int k = 0; k < 64; k += 4) {
            float4 w0 = *(float4*)(sW1 + (k + 0) * 256 + tx * 4);
            float4 w1 = *(float4*)(sW1 + (k + 1) * 256 + tx * 4);
            float4 w2 = *(float4*)(sW1 + (k + 2) * 256 + tx * 4);
            float4 w3 = *(float4*)(sW1 + (k + 3) * 256 + tx * 4);
            #pragma unroll
            for (int i = 0; i < 8; i++) {
                float4 a = *(float4*)(sA + (ty * 8 + i) * 68 + k);
                acc[i][0] += a.x * w0.x; acc[i][1] += a.x * w0.y;
                acc[i][2] += a.x * w0.z; acc[i][3] += a.x * w0.w;
                acc[i][0] += a.y * w1.x; acc[i][1] += a.y * w1.y;
                acc[i][2] += a.y * w1.z; acc[i][3] += a.y * w1.w;
                acc[i][0] += a.z * w2.x; acc[i][1] += a.z * w2.y;
                acc[i][2] += a.z * w2.z; acc[i][3] += a.z * w2.w;
                acc[i][0] += a.w * w3.x; acc[i][1] += a.w * w3.y;
                acc[i][2] += a.w * w3.z; acc[i][3] += a.w * w3.w;
            }
        }
        float ls[8], lq[8];
        #pragma unroll
        for (int i = 0; i < 8; i++) {
            acc[i][0] = silu_f(acc[i][0] + b1v.x);
            acc[i][1] = silu_f(acc[i][1] + b1v.y);
            acc[i][2] = silu_f(acc[i][2] + b1v.z);
            acc[i][3] = silu_f(acc[i][3] + b1v.w);
            ls[i] = (acc[i][0] + acc[i][1]) + (acc[i][2] + acc[i][3]);
            lq[i] = acc[i][0] * acc[i][0] + acc[i][1] * acc[i][1] +
                    acc[i][2] * acc[i][2] + acc[i][3] * acc[i][3];
        }
        #pragma unroll
        for (int i = 0; i < 8; i++) {
            float s = ls[i], q = lq[i];
            #pragma unroll
            for (int m2 = 1; m2 < 32; m2 <<= 1) {
                s += __shfl_xor_sync(0xffffffffu, s, m2);
                q += __shfl_xor_sync(0xffffffffu, q, m2);
            }
            ls[i] = s; lq[i] = q;
        }
        if ((tid & 31) == 0) {
            #pragma unroll
            for (int i = 0; i < 8; i++) {
                sRed[warp * 16 + i * 2] = ls[i];
                sRed[warp * 16 + i * 2 + 1] = lq[i];
            }
        }
        __syncthreads();
        int wb = (ty * 2) * 16;
        #pragma unroll
        for (int i = 0; i < 8; i++) {
            float S = sRed[wb + i * 2] + sRed[wb + 16 + i * 2];
            float Q = sRed[wb + i * 2 + 1] + sRed[wb + 16 + i * 2 + 1];
            float mean = S * (1.f / 256.f);
            float var = Q * (1.f / 256.f) - mean * mean;
            float rstd = rsqrtf(var + 1e-5f);
            float4 n;
            n.x = (acc[i][0] - mean) * rstd * gv.x + bnv.x;
            n.y = (acc[i][1] - mean) * rstd * gv.y + bnv.y;
            n.z = (acc[i][2] - mean) * rstd * gv.z + bnv.z;
            n.w = (acc[i][3] - mean) * rstd * gv.w + bnv.w;
            *(float4*)(sT + (ty * 8 + i) * 260 + tx * 4) = n;
        }
        __syncthreads();
        float a2[2][4];
        #pragma unroll
        for (int i = 0; i < 2; i++)
            #pragma unroll
            for (int j = 0; j < 4; j++) a2[i][j] = 0.f;
        #pragma unroll 4
        for (int k = 0; k < 256; k += 4) {
            float4 w0 = *(float4*)(sW2 + (k + 0) * 64 + cx * 4);
            float4 w1 = *(float4*)(sW2 + (k + 1) * 64 + cx * 4);
            float4 w2 = *(float4*)(sW2 + (k + 2) * 64 + cx * 4);
            float4 w3 = *(float4*)(sW2 + (k + 3) * 64 + cx * 4);
            float4 a0 = *(float4*)(sT + (ry * 2) * 260 + k);
            float4 a1 = *(float4*)(sT + (ry * 2 + 1) * 260 + k);
            a2[0][0] += a0.x * w0.x; a2[0][1] += a0.x * w0.y; a2[0][2] += a0.x * w0.z; a2[0][3] += a0.x * w0.w;
            a2[0][0] += a0.y * w1.x; a2[0][1] += a0.y * w1.y; a2[0][2] += a0.y * w1.z; a2[0][3] += a0.y * w1.w;
            a2[0][0] += a0.z * w2.x; a2[0][1] += a0.z * w2.y; a2[0][2] += a0.z * w2.z; a2[0][3] += a0.z * w2.w;
            a2[0][0] += a0.w * w3.x; a2[0][1] += a0.w * w3.y; a2[0][2] += a0.w * w3.z; a2[0][3] += a0.w * w3.w;
            a2[1][0] += a1.x * w0.x; a2[1][1] += a1.x * w0.y; a2[1][2] += a1.x * w0.z; a2[1][3] += a1.x * w0.w;
            a2[1][0] += a1.y * w1.x; a2[1][1] += a1.y * w1.y; a2[1][2] += a1.y * w1.z; a2[1][3] += a1.y * w1.w;
            a2[1][0] += a1.z * w2.x; a2[1][1] += a1.z * w2.y; a2[1][2] += a1.z * w2.z; a2[1][3] += a1.z * w2.w;
            a2[1][0] += a1.w * w3.x; a2[1][1] += a1.w * w3.y; a2[1][2] += a1.w * w3.z; a2[1][3] += a1.w * w3.w;
        }
        int r0 = base + ry * 2;
        float4 o0 = make_float4(a2[0][0] + b2v.x, a2[0][1] + b2v.y, a2[0][2] + b2v.z, a2[0][3] + b2v.w);
        float4 o1 = make_float4(a2[1][0] + b2v.x, a2[1][1] + b2v.y, a2[1][2] + b2v.z, a2[1][3] + b2v.w);
        *(float4*)(hout + (long)r0 * 64 + cx * 4) = o0;
        *(float4*)(hout + (long)(r0 + 1) * 64 + cx * 4) = o1;
    }
}

// ---------------- graph pooling: mean | max | sum | root ----------------
__global__ __launch_bounds__(256) void pool_kernel(const float* __restrict__ h,
                                                   const float* __restrict__ x,
                                                   const int* __restrict__ ptr,
                                                   float* __restrict__ o) {
    int g = blockIdx.x;
    int start = ptr[g], end = ptr[g + 1];
    int tid = threadIdx.x;
    int rl = tid >> 6, d = tid & 63;
    float sm = 0.f, mx = -INFINITY;
    for (int r = start + rl; r < end; r += 4) {
        float v = h[(long)r * 64 + d];
        sm += v;
        mx = fmaxf(mx, v);
    }
    __shared__ float sS[4][64], sM[4][64];
    sS[rl][d] = sm; sM[rl][d] = mx;
    __syncthreads();
    if (tid < 64) {
        float s = sS[0][tid] + sS[1][tid] + sS[2][tid] + sS[3][tid];
        float m = fmaxf(fmaxf(sM[0][tid], sM[1][tid]), fmaxf(sM[2][tid], sM[3][tid]));
        int cnt = end - start;
        float mean = s / (float)(cnt > 0 ? cnt : 1);
        if (m == -INFINITY) m = 0.f;
        o[g * 196 + tid] = mean;
        o[g * 196 + 64 + tid] = m;
        o[g * 196 + 128 + tid] = s;
    }
    if (tid < 4) o[g * 196 + 192 + tid] = x[(long)start * 4 + tid];
}

// ---------------- readout: silu(o@W1+b1) -> LN -> @W2+b2 ----------------
__global__ __launch_bounds__(256) void readout_kernel(
    const float* __restrict__ o, const float* __restrict__ W1, const float* __restrict__ b1,
    const float* __restrict__ gg, const float* __restrict__ bn,
    const float* __restrict__ W2, const float* __restrict__ b2, float* __restrict__ out) {
    int g = blockIdx.x;
    int tid = threadIdx.x;
    __shared__ float so[196];
    __shared__ float red[256];
    __shared__ float ws[8][2];
    __shared__ float stats[2];
    if (tid < 196) so[tid] = o[g * 196 + tid];
    __syncthreads();
    float acc = __ldg(b1 + tid);
    #pragma unroll 4
    for (int k = 0; k < 196; k++) acc += so[k] * __ldg(W1 + k * 256 + tid);
    float s = silu_f(acc);
    float ls = s, lq = s * s;
    #pragma unroll
    for (int m2 = 1; m2 < 32; m2 <<= 1) {
        ls += __shfl_xor_sync(0xffffffffu, ls, m2);
        lq += __shfl_xor_sync(0xffffffffu, lq, m2);
    }
    int w = tid >> 5;
    if ((tid & 31) == 0) { ws[w][0] = ls; ws[w][1] = lq; }
    __syncthreads();
    if (tid == 0) {
        float S = 0.f, Q = 0.f;
        for (int i = 0; i < 8; i++) { S += ws[i][0]; Q += ws[i][1]; }
        stats[0] = S; stats[1] = Q;
    }
    __syncthreads();
    float mean = stats[0] * (1.f / 256.f);
    float var = stats[1] * (1.f / 256.f) - mean * mean;
    float rstd = rsqrtf(var + 1e-5f);
    float n = (s - mean) * rstd * __ldg(gg + tid) + __ldg(bn + tid);
    float4 w2 = *(const float4*)(W2 + tid * 4);
    float p[4] = {n * w2.x, n * w2.y, n * w2.z, n * w2.w};
    for (int j = 0; j < 4; j++) {
        red[tid] = p[j];
        __syncthreads();
        for (int st = 128; st > 0; st >>= 1) {
            if (tid < st) red[tid] += red[tid + st];
            __syncthreads();
        }
        if (tid == 0) out[g * 4 + j] = red[0] + __ldg(b2 + j);
        __syncthreads();
    }
}

// ---------------- launch ----------------
extern "C" void kernel_launch(void* const* d_in, const int* in_sizes, int n_in,
                              void* d_out, int out_size) {
    const float* x      = (const float*)d_in[0];
    const int*   ei     = (const int*)d_in[1];
    const int*   ptr    = (const int*)d_in[3];
    const float* Wl0    = (const float*)d_in[4];
    const float* bl0    = (const float*)d_in[5];
    const float* Wr0    = (const float*)d_in[6];
    const float* Wl     = (const float*)d_in[7];
    const float* bl     = (const float*)d_in[8];
    const float* Wr     = (const float*)d_in[9];
    const float* Wres   = (const float*)d_in[10];
    const float* bres   = (const float*)d_in[11];
    const float* ln_g   = (const float*)d_in[12];
    const float* ln_b   = (const float*)d_in[13];
    const float* mlp_W1 = (const float*)d_in[14];
    const float* mlp_b1 = (const float*)d_in[15];
    const float* mlp_g  = (const float*)d_in[16];
    const float* mlp_bn = (const float*)d_in[17];
    const float* mlp_W2 = (const float*)d_in[18];
    const float* mlp_b2 = (const float*)d_in[19];
    const float* ro_W1  = (const float*)d_in[20];
    const float* ro_b1  = (const float*)d_in[21];
    const float* ro_g   = (const float*)d_in[22];
    const float* ro_bn  = (const float*)d_in[23];
    const float* ro_W2  = (const float*)d_in[24];
    const float* ro_b2  = (const float*)d_in[25];
    float* out = (float*)d_out;

    void* p;
    cudaGetSymbolAddress(&p, g_deg);    int* deg = (int*)p;
    cudaGetSymbolAddress(&p, g_incl);   int* incl = (int*)p;
    cudaGetSymbolAddress(&p, g_rowptr); int* rowptr = (int*)p;
    cudaGetSymbolAddress(&p, g_cur);    int* cur = (int*)p;
    cudaGetSymbolAddress(&p, g_bsums);  int* bsums = (int*)p;
    cudaGetSymbolAddress(&p, g_csr);    int* csr = (int*)p;
    cudaGetSymbolAddress(&p, g_hA);     float* hA = (float*)p;
    cudaGetSymbolAddress(&p, g_hB);     float* hB = (float*)p;
    cudaGetSymbolAddress(&p, g_obuf);   float* obuf = (float*)p;

    cudaFuncSetAttribute(sage_fused_kernel, cudaFuncAttributeMaxDynamicSharedMemorySize, SG_SMEM);
    cudaFuncSetAttribute(mlp_kernel, cudaFuncAttributeMaxDynamicSharedMemorySize, MLP_SMEM);

    zero_deg_kernel<<<(NN + 255) / 256, 256>>>(deg);
    hist_kernel<<<(NE + 255) / 256, 256>>>(ei, deg);
    scan1_kernel<<<(NN + 1023) / 1024, 1024>>>(deg, incl, bsums);
    scan2_kernel<<<1, 128>>>(bsums, (NN + 1023) / 1024);
    scan3_kernel<<<(NN + 255) / 256, 256>>>(incl, deg, bsums, rowptr, cur);
    scatter_kernel<<<(NE + 255) / 256, 256>>>(ei, cur, csr);

    layer0_kernel<<<(NN + 3) / 4, 256>>>(x, rowptr, csr, Wl0, bl0, Wr0, Wres, bres,
                                         ln_g, ln_b, hA);

    const float* hin = hA;
    float* hout = hB;
    for (int i = 0; i < 3; i++) {
        sage_fused_kernel<<<296, 256, SG_SMEM>>>(hin, rowptr, csr, Wl + i * 128 * 64,
                                                 bl + i * 64, Wr + i * 64 * 64,
                                                 ln_g + (i + 1) * 64, ln_b + (i + 1) * 64, hout);
        const float* tmp = hin;
        hin = hout;
        hout = (float*)tmp;
    }
    // hin == hB (final sage output), hout == hA
    mlp_kernel<<<148, 256, MLP_SMEM>>>(hin, mlp_W1, mlp_b1, mlp_g, mlp_bn, mlp_W2, mlp_b2, hout);
    pool_kernel<<<NG, 256>>>(hout, x, ptr, obuf);
    readout_kernel<<<NG, 256>>>(obuf, ro_W1, ro_b1, ro_g, ro_bn, ro_W2, ro_b2, out);
}

// round 3
// speedup vs baseline: 1.1819x; 1.1819x over previous
#include <cuda_runtime.h>
#include <math.h>

#define NN 100000
#define NE 1600000
#define NG 200
#define HID 64

// ---------------- scratch (static device globals; no allocation) ----------------
__device__ int   g_deg[NN];
__device__ int   g_incl[NN];
__device__ int   g_rowptr[NN + 1];
__device__ int   g_cur[NN];
__device__ int   g_bsums[256];
__device__ int   g_csr[NE];
__device__ float g_hA[NN * HID];
__device__ float g_hB[NN * HID];
__device__ float g_agg[NN * 128];
__device__ float g_obuf[NG * 196];

__device__ __forceinline__ float silu_f(float z) { return z / (1.f + __expf(-z)); }

// ---------------- CSR build ----------------
__global__ void zero_deg_kernel(int* deg) {
    int i = blockIdx.x * blockDim.x + threadIdx.x;
    if (i < NN) deg[i] = 0;
}

__global__ void hist_kernel(const int* __restrict__ ei, int* __restrict__ deg) {
    int e = blockIdx.x * blockDim.x + threadIdx.x;
    if (e < NE) atomicAdd(&deg[ei[NE + e]], 1);
}

__global__ void scan1_kernel(const int* __restrict__ deg, int* __restrict__ incl,
                             int* __restrict__ bsums) {
    __shared__ int s[1024];
    int tid = threadIdx.x;
    int i = blockIdx.x * 1024 + tid;
    s[tid] = (i < NN) ? deg[i] : 0;
    __syncthreads();
    for (int off = 1; off < 1024; off <<= 1) {
        int v = (tid >= off) ? s[tid - off] : 0;
        __syncthreads();
        s[tid] += v;
        __syncthreads();
    }
    if (i < NN) incl[i] = s[tid];
    if (tid == 1023) bsums[blockIdx.x] = s[1023];
}

__global__ void scan2_kernel(int* bsums, int nb) {
    __shared__ int s[128];
    int tid = threadIdx.x;
    int v = (tid < nb) ? bsums[tid] : 0;
    s[tid] = v;
    __syncthreads();
    for (int off = 1; off < 128; off <<= 1) {
        int t = (tid >= off) ? s[tid - off] : 0;
        __syncthreads();
        s[tid] += t;
        __syncthreads();
    }
    if (tid < nb) bsums[tid] = s[tid] - v;  // exclusive
}

__global__ void scan3_kernel(const int* __restrict__ incl, const int* __restrict__ deg,
                             const int* __restrict__ bsums, int* __restrict__ rowptr,
                             int* __restrict__ cur) {
    int i = blockIdx.x * blockDim.x + threadIdx.x;
    if (i < NN) {
        int val = incl[i] + bsums[i >> 10];
        rowptr[i + 1] = val;
        cur[i] = val - deg[i];
    }
    if (i == 0) rowptr[0] = 0;
}

__global__ void scatter_kernel(const int* __restrict__ ei, int* __restrict__ cur,
                               int* __restrict__ csr) {
    int e = blockIdx.x * blockDim.x + threadIdx.x;
    if (e < NE) {
        int d = ei[NE + e];
        int p = atomicAdd(&cur[d], 1);
        csr[p] = ei[e];
    }
}

// ---------------- layer 0 (IN=4): fully fused sage + LN + x_res + silu ----------------
__global__ __launch_bounds__(256) void layer0_kernel(
    const float* __restrict__ x, const int* __restrict__ rowptr, const int* __restrict__ csr,
    const float* __restrict__ Wl0, const float* __restrict__ bl0, const float* __restrict__ Wr0,
    const float* __restrict__ Wres, const float* __restrict__ bres,
    const float* __restrict__ lng, const float* __restrict__ lnb, float* __restrict__ hout) {
    int tid = threadIdx.x;
    int grp = tid >> 6;
    int l = tid & 63;
    int v = blockIdx.x * 4 + grp;
    bool valid = (v < NN);
    __shared__ float sMx[4][64], sSm[4][64], sAgg[4][8], sX[4][4], sP[4][2][2];
    int start = 0, end = 0;
    if (valid) { start = rowptr[v]; end = rowptr[v + 1]; }
    if (valid && l < 4) sX[grp][l] = x[v * 4 + l];
    int es = l >> 2, dim = l & 3;
    float mx = -INFINITY, sm = 0.f;
    for (int e = start + es; e < end; e += 16) {
        int s = csr[e];
        float val = x[s * 4 + dim];
        mx = fmaxf(mx, val);
        sm += val;
    }
    sMx[grp][l] = mx; sSm[grp][l] = sm;
    __syncthreads();
    if (l < 8) {
        int dd = l & 3;
        int deg = end - start;
        if (l < 4) {
            float m = -INFINITY;
            #pragma unroll
            for (int j = 0; j < 16; j++) m = fmaxf(m, sMx[grp][j * 4 + dd]);
            sAgg[grp][dd] = (deg > 0) ? m : 0.f;
        } else {
            float s2 = 0.f;
            #pragma unroll
            for (int j = 0; j < 16; j++) s2 += sSm[grp][j * 4 + dd];
            sAgg[grp][4 + dd] = s2 / (float)(deg > 0 ? deg : 1);
        }
    }
    __syncthreads();
    float acc = __ldg(bl0 + l);
    #pragma unroll
    for (int k = 0; k < 8; k++) acc += sAgg[grp][k] * __ldg(Wl0 + k * 64 + l);
    float xres = __ldg(bres + l);
    #pragma unroll
    for (int k = 0; k < 4; k++) {
        float xv = sX[grp][k];
        acc += xv * __ldg(Wr0 + k * 64 + l);
        xres += xv * __ldg(Wres + k * 64 + l);
    }
    float s1 = acc, q1 = acc * acc;
    #pragma unroll
    for (int m2 = 1; m2 < 32; m2 <<= 1) {
        s1 += __shfl_xor_sync(0xffffffffu, s1, m2);
        q1 += __shfl_xor_sync(0xffffffffu, q1, m2);
    }
    int w = (tid >> 5) & 1;
    if ((tid & 31) == 0) { sP[grp][w][0] = s1; sP[grp][w][1] = q1; }
    __syncthreads();
    float S = sP[grp][0][0] + sP[grp][1][0];
    float Q = sP[grp][0][1] + sP[grp][1][1];
    float mean = S * (1.f / 64.f);
    float var = Q * (1.f / 64.f) - mean * mean;
    float rstd = rsqrtf(var + 1e-5f);
    float z = (acc - mean) * rstd * __ldg(lng + l) + __ldg(lnb + l) + xres;
    if (valid) hout[v * 64 + l] = silu_f(z);
}

// ---------------- aggregation (hidden layers): WIDE grid, 8-unrolled gather ---------
__global__ __launch_bounds__(256) void agg_kernel(const float* __restrict__ hin,
                                                  const int* __restrict__ rowptr,
                                                  const int* __restrict__ csr,
                                                  float* __restrict__ aggout) {
    int tid = threadIdx.x;
    int grp = tid >> 6;
    int l = tid & 63;
    int v = blockIdx.x * 4 + grp;
    if (v >= NN) return;
    int start = rowptr[v], end = rowptr[v + 1];
    float mx = -INFINITY, sm = 0.f;
    int e = start;
    for (; e + 8 <= end; e += 8) {
        int i0 = csr[e], i1 = csr[e + 1], i2 = csr[e + 2], i3 = csr[e + 3];
        int i4 = csr[e + 4], i5 = csr[e + 5], i6 = csr[e + 6], i7 = csr[e + 7];
        float v0 = hin[i0 * 64 + l], v1 = hin[i1 * 64 + l];
        float v2 = hin[i2 * 64 + l], v3 = hin[i3 * 64 + l];
        float v4 = hin[i4 * 64 + l], v5 = hin[i5 * 64 + l];
        float v6 = hin[i6 * 64 + l], v7 = hin[i7 * 64 + l];
        mx = fmaxf(mx, fmaxf(fmaxf(v0, v1), fmaxf(v2, v3)));
        mx = fmaxf(mx, fmaxf(fmaxf(v4, v5), fmaxf(v6, v7)));
        sm += ((v0 + v1) + (v2 + v3)) + ((v4 + v5) + (v6 + v7));
    }
    for (; e < end; e++) {
        float vv = hin[csr[e] * 64 + l];
        mx = fmaxf(mx, vv);
        sm += vv;
    }
    int deg = end - start;
    aggout[v * 128 + l] = (deg > 0) ? mx : 0.f;
    aggout[v * 128 + 64 + l] = sm / (float)(deg > 0 ? deg : 1);
}

// ---------------- sage GEMM + LN + residual + silu (hidden layers) ----------------
// A-panel per 64-node tile in smem: cols [0:128)=agg(max|mean), [128:192)=own feats.
// Persistent blocks; float4 k-unrolled inner loop.
#define SAH_STRIDE 196
#define SG_SMEM ((192 * 64 + 64 * SAH_STRIDE) * 4)
__global__ __launch_bounds__(256) void sage_gemm_kernel(
    const float* __restrict__ agg, const float* __restrict__ hin,
    const float* __restrict__ Wl, const float* __restrict__ bl, const float* __restrict__ Wr,
    const float* __restrict__ lng, const float* __restrict__ lnb, float* __restrict__ hout) {
    extern __shared__ float smem[];
    float* sW = smem;                  // 192 x 64
    float* sAH = sW + 192 * 64;        // 64 x 196
    int tid = threadIdx.x;
    for (int i = tid; i < 128 * 64 / 4; i += 256) ((float4*)sW)[i] = ((const float4*)Wl)[i];
    for (int i = tid; i < 64 * 64 / 4; i += 256)
        ((float4*)(sW + 128 * 64))[i] = ((const float4*)Wr)[i];
    int ty = tid >> 4, tx = tid & 15;
    float4 bv = *(const float4*)(bl + tx * 4);
    float4 gv = *(const float4*)(lng + tx * 4);
    float4 lbv = *(const float4*)(lnb + tx * 4);
    const int NT = (NN + 63) >> 6;
    for (int t = blockIdx.x; t < NT; t += gridDim.x) {
        __syncthreads();
        int base = t * 64;
        // agg -> cols 0..127
        for (int i = tid; i < 64 * 32; i += 256) {
            int r = i >> 5, c = i & 31;
            int row = base + r;
            float4 vv = make_float4(0.f, 0.f, 0.f, 0.f);
            if (row < NN) vv = ((const float4*)(agg + (long)row * 128))[c];
            *(float4*)(sAH + r * SAH_STRIDE + c * 4) = vv;
        }
        // own features -> cols 128..191
        for (int i = tid; i < 64 * 16; i += 256) {
            int r = i >> 4, c = i & 15;
            int row = base + r;
            float4 vv = make_float4(0.f, 0.f, 0.f, 0.f);
            if (row < NN) vv = ((const float4*)(hin + (long)row * 64))[c];
            *(float4*)(sAH + r * SAH_STRIDE + 128 + c * 4) = vv;
        }
        __syncthreads();
        float acc[4][4];
        #pragma unroll
        for (int i = 0; i < 4; i++)
            #pragma unroll
            for (int j = 0; j < 4; j++) acc[i][j] = 0.f;
        #pragma unroll 2
        for (int k = 0; k < 192; k += 4) {
            float4 w0 = *(float4*)(sW + (k + 0) * 64 + tx * 4);
            float4 w1 = *(float4*)(sW + (k + 1) * 64 + tx * 4);
            float4 w2 = *(float4*)(sW + (k + 2) * 64 + tx * 4);
            float4 w3 = *(float4*)(sW + (k + 3) * 64 + tx * 4);
            #pragma unroll
            for (int i = 0; i < 4; i++) {
                float4 a = *(float4*)(sAH + (ty * 4 + i) * SAH_STRIDE + k);
                acc[i][0] += a.x * w0.x; acc[i][1] += a.x * w0.y;
                acc[i][2] += a.x * w0.z; acc[i][3] += a.x * w0.w;
                acc[i][0] += a.y * w1.x; acc[i][1] += a.y * w1.y;
                acc[i][2] += a.y * w1.z; acc[i][3] += a.y * w1.w;
                acc[i][0] += a.z * w2.x; acc[i][1] += a.z * w2.y;
                acc[i][2] += a.z * w2.z; acc[i][3] += a.z * w2.w;
                acc[i][0] += a.w * w3.x; acc[i][1] += a.w * w3.y;
                acc[i][2] += a.w * w3.z; acc[i][3] += a.w * w3.w;
            }
        }
        #pragma unroll
        for (int i = 0; i < 4; i++) {
            float v0 = acc[i][0] + bv.x;
            float v1 = acc[i][1] + bv.y;
            float v2 = acc[i][2] + bv.z;
            float v3 = acc[i][3] + bv.w;
            float s = (v0 + v1) + (v2 + v3);
            float q = v0 * v0 + v1 * v1 + v2 * v2 + v3 * v3;
            #pragma unroll
            for (int m2 = 1; m2 < 16; m2 <<= 1) {
                s += __shfl_xor_sync(0xffffffffu, s, m2);
                q += __shfl_xor_sync(0xffffffffu, q, m2);
            }
            float mean = s * (1.f / 64.f);
            float var = q * (1.f / 64.f) - mean * mean;
            float rstd = rsqrtf(var + 1e-5f);
            int row = ty * 4 + i;
            int grow = base + row;
            if (grow < NN) {
                const float* hr = sAH + row * SAH_STRIDE + 128 + tx * 4;
                float4 o;
                o.x = silu_f((v0 - mean) * rstd * gv.x + lbv.x + hr[0]);
                o.y = silu_f((v1 - mean) * rstd * gv.y + lbv.y + hr[1]);
                o.z = silu_f((v2 - mean) * rstd * gv.z + lbv.z + hr[2]);
                o.w = silu_f((v3 - mean) * rstd * gv.w + lbv.w + hr[3]);
                *(float4*)(hout + (long)grow * 64 + tx * 4) = o;
            }
        }
    }
}

// ---------------- node MLP: silu(h@W1+b1) -> LN -> @W2+b2, fused ----------------
#define MLP_SMEM ((64 * 256 + 256 * 64 + 32 * 68 + 32 * 260 + 128) * 4)
__global__ __launch_bounds__(256) void mlp_kernel(
    const float* __restrict__ hin, const float* __restrict__ W1, const float* __restrict__ b1,
    const float* __restrict__ gg, const float* __restrict__ bn,
    const float* __restrict__ W2, const float* __restrict__ b2, float* __restrict__ hout) {
    extern __shared__ float smem[];
    float* sW1 = smem;               // 64*256
    float* sW2 = sW1 + 64 * 256;     // 256*64
    float* sA = sW2 + 256 * 64;      // 32 x 68
    float* sT = sA + 32 * 68;        // 32 x 260
    float* sRed = sT + 32 * 260;     // 8 warps * 16
    int tid = threadIdx.x;
    for (int i = tid; i < 64 * 256 / 4; i += 256) ((float4*)sW1)[i] = ((const float4*)W1)[i];
    for (int i = tid; i < 256 * 64 / 4; i += 256) ((float4*)sW2)[i] = ((const float4*)W2)[i];
    int ty = tid >> 6, tx = tid & 63;
    int ry = tid >> 4, cx = tid & 15;
    int warp = tid >> 5;
    float4 b1v = *(const float4*)(b1 + tx * 4);
    float4 gv = *(const float4*)(gg + tx * 4);
    float4 bnv = *(const float4*)(bn + tx * 4);
    float4 b2v = *(const float4*)(b2 + cx * 4);
    const int NT = NN / 32;  // 3125 exact
    for (int t = blockIdx.x; t < NT; t += gridDim.x) {
        __syncthreads();
        int base = t * 32;
        for (int i = tid; i < 32 * 16; i += 256) {
            int r = i >> 4, c = i & 15;
            ((float4*)(sA + r * 68))[c] = ((const float4*)(hin + (long)(base + r) * 64))[c];
        }
        __syncthreads();
        float acc[8][4];
        #pragma unroll
        for (int i = 0; i < 8; i++)
            #pragma unroll
            for (int j = 0; j < 4; j++) acc[i][j] = 0.f;
        #pragma unroll 2
        for (int k = 0; k < 64; k += 4) {
            float4 w0 = *(float4*)(sW1 + (k + 0) * 256 + tx * 4);
            float4 w1 = *(float4*)(sW1 + (k + 1) * 256 + tx * 4);
            float4 w2 = *(float4*)(sW1 + (k + 2) * 256 + tx * 4);
            float4 w3 = *(float4*)(sW1 + (k + 3) * 256 + tx * 4);
            #pragma unroll
            for (int i = 0; i < 8; i++) {
                float4 a = *(float4*)(sA + (ty * 8 + i) * 68 + k);
                acc[i][0] += a.x * w0.x; acc[i][1] += a.x * w0.y;
                acc[i][2] += a.x * w0.z; acc[i][3] += a.x * w0.w;
                acc[i][0] += a.y * w1.x; acc[i][1] += a.y * w1.y;
                acc[i][2] += a.y * w1.z; acc[i][3] += a.y * w1.w;
                acc[i][0] += a.z * w2.x; acc[i][1] += a.z * w2.y;
                acc[i][2] += a.z * w2.z; acc[i][3] += a.z * w2.w;
                acc[i][0] += a.w * w3.x; acc[i][1] += a.w * w3.y;
                acc[i][2] += a.w * w3.z; acc[i][3] += a.w * w3.w;
            }
        }
        float ls[8], lq[8];
        #pragma unroll
        for (int i = 0; i < 8; i++) {
            acc[i][0] = silu_f(acc[i][0] + b1v.x);
            acc[i][1] = silu_f(acc[i][1] + b1v.y);
            acc[i][2] = silu_f(acc[i][2] + b1v.z);
            acc[i][3] = silu_f(acc[i][3] + b1v.w);
            ls[i] = (acc[i][0] + acc[i][1]) + (acc[i][2] + acc[i][3]);
            lq[i] = acc[i][0] * acc[i][0] + acc[i][1] * acc[i][1] +
                    acc[i][2] * acc[i][2] + acc[i][3] * acc[i][3];
        }
        #pragma unroll
        for (int i = 0; i < 8; i++) {
            float s = ls[i], q = lq[i];
            #pragma unroll
            for (int m2 = 1; m2 < 32; m2 <<= 1) {
                s += __shfl_xor_sync(0xffffffffu, s, m2);
                q += __shfl_xor_sync(0xffffffffu, q, m2);
            }
            ls[i] = s; lq[i] = q;
        }
        if ((tid & 31) == 0) {
            #pragma unroll
            for (int i = 0; i < 8; i++) {
                sRed[warp * 16 + i * 2] = ls[i];
                sRed[warp * 16 + i * 2 + 1] = lq[i];
            }
        }
        __syncthreads();
        int wb = (ty * 2) * 16;
        #pragma unroll
        for (int i = 0; i < 8; i++) {
            float S = sRed[wb + i * 2] + sRed[wb + 16 + i * 2];
            float Q = sRed[wb + i * 2 + 1] + sRed[wb + 16 + i * 2 + 1];
            float mean = S * (1.f / 256.f);
            float var = Q * (1.f / 256.f) - mean * mean;
            float rstd = rsqrtf(var + 1e-5f);
            float4 n;
            n.x = (acc[i][0] - mean) * rstd * gv.x + bnv.x;
            n.y = (acc[i][1] - mean) * rstd * gv.y + bnv.y;
            n.z = (acc[i][2] - mean) * rstd * gv.z + bnv.z;
            n.w = (acc[i][3] - mean) * rstd * gv.w + bnv.w;
            *(float4*)(sT + (ty * 8 + i) * 260 + tx * 4) = n;
        }
        __syncthreads();
        float a2[2][4];
        #pragma unroll
        for (int i = 0; i < 2; i++)
            #pragma unroll
            for (int j = 0; j < 4; j++) a2[i][j] = 0.f;
        #pragma unroll 4
        for (int k = 0; k < 256; k += 4) {
            float4 w0 = *(float4*)(sW2 + (k + 0) * 64 + cx * 4);
            float4 w1 = *(float4*)(sW2 + (k + 1) * 64 + cx * 4);
            float4 w2 = *(float4*)(sW2 + (k + 2) * 64 + cx * 4);
            float4 w3 = *(float4*)(sW2 + (k + 3) * 64 + cx * 4);
            float4 a0 = *(float4*)(sT + (ry * 2) * 260 + k);
            float4 a1 = *(float4*)(sT + (ry * 2 + 1) * 260 + k);
            a2[0][0] += a0.x * w0.x; a2[0][1] += a0.x * w0.y; a2[0][2] += a0.x * w0.z; a2[0][3] += a0.x * w0.w;
            a2[0][0] += a0.y * w1.x; a2[0][1] += a0.y * w1.y; a2[0][2] += a0.y * w1.z; a2[0][3] += a0.y * w1.w;
            a2[0][0] += a0.z * w2.x; a2[0][1] += a0.z * w2.y; a2[0][2] += a0.z * w2.z; a2[0][3] += a0.z * w2.w;
            a2[0][0] += a0.w * w3.x; a2[0][1] += a0.w * w3.y; a2[0][2] += a0.w * w3.z; a2[0][3] += a0.w * w3.w;
            a2[1][0] += a1.x * w0.x; a2[1][1] += a1.x * w0.y; a2[1][2] += a1.x * w0.z; a2[1][3] += a1.x * w0.w;
            a2[1][0] += a1.y * w1.x; a2[1][1] += a1.y * w1.y; a2[1][2] += a1.y * w1.z; a2[1][3] += a1.y * w1.w;
            a2[1][0] += a1.z * w2.x; a2[1][1] += a1.z * w2.y; a2[1][2] += a1.z * w2.z; a2[1][3] += a1.z * w2.w;
            a2[1][0] += a1.w * w3.x; a2[1][1] += a1.w * w3.y; a2[1][2] += a1.w * w3.z; a2[1][3] += a1.w * w3.w;
        }
        int r0 = base + ry * 2;
        float4 o0 = make_float4(a2[0][0] + b2v.x, a2[0][1] + b2v.y, a2[0][2] + b2v.z, a2[0][3] + b2v.w);
        float4 o1 = make_float4(a2[1][0] + b2v.x, a2[1][1] + b2v.y, a2[1][2] + b2v.z, a2[1][3] + b2v.w);
        *(float4*)(hout + (long)r0 * 64 + cx * 4) = o0;
        *(float4*)(hout + (long)(r0 + 1) * 64 + cx * 4) = o1;
    }
}

// ---------------- graph pooling: mean | max | sum | root ----------------
__global__ __launch_bounds__(256) void pool_kernel(const float* __restrict__ h,
                                                   const float* __restrict__ x,
                                                   const int* __restrict__ ptr,
                                                   float* __restrict__ o) {
    int g = blockIdx.x;
    int start = ptr[g], end = ptr[g + 1];
    int tid = threadIdx.x;
    int rl = tid >> 6, d = tid & 63;
    float sm = 0.f, mx = -INFINITY;
    for (int r = start + rl; r < end; r += 4) {
        float v = h[(long)r * 64 + d];
        sm += v;
        mx = fmaxf(mx, v);
    }
    __shared__ float sS[4][64], sM[4][64];
    sS[rl][d] = sm; sM[rl][d] = mx;
    __syncthreads();
    if (tid < 64) {
        float s = sS[0][tid] + sS[1][tid] + sS[2][tid] + sS[3][tid];
        float m = fmaxf(fmaxf(sM[0][tid], sM[1][tid]), fmaxf(sM[2][tid], sM[3][tid]));
        int cnt = end - start;
        float mean = s / (float)(cnt > 0 ? cnt : 1);
        if (m == -INFINITY) m = 0.f;
        o[g * 196 + tid] = mean;
        o[g * 196 + 64 + tid] = m;
        o[g * 196 + 128 + tid] = s;
    }
    if (tid < 4) o[g * 196 + 192 + tid] = x[(long)start * 4 + tid];
}

// ---------------- readout: silu(o@W1+b1) -> LN -> @W2+b2 ----------------
__global__ __launch_bounds__(256) void readout_kernel(
    const float* __restrict__ o, const float* __restrict__ W1, const float* __restrict__ b1,
    const float* __restrict__ gg, const float* __restrict__ bn,
    const float* __restrict__ W2, const float* __restrict__ b2, float* __restrict__ out) {
    int g = blockIdx.x;
    int tid = threadIdx.x;
    __shared__ float so[196];
    __shared__ float red[256];
    __shared__ float ws[8][2];
    __shared__ float stats[2];
    if (tid < 196) so[tid] = o[g * 196 + tid];
    __syncthreads();
    float acc = __ldg(b1 + tid);
    #pragma unroll 4
    for (int k = 0; k < 196; k++) acc += so[k] * __ldg(W1 + k * 256 + tid);
    float s = silu_f(acc);
    float ls = s, lq = s * s;
    #pragma unroll
    for (int m2 = 1; m2 < 32; m2 <<= 1) {
        ls += __shfl_xor_sync(0xffffffffu, ls, m2);
        lq += __shfl_xor_sync(0xffffffffu, lq, m2);
    }
    int w = tid >> 5;
    if ((tid & 31) == 0) { ws[w][0] = ls; ws[w][1] = lq; }
    __syncthreads();
    if (tid == 0) {
        float S = 0.f, Q = 0.f;
        for (int i = 0; i < 8; i++) { S += ws[i][0]; Q += ws[i][1]; }
        stats[0] = S; stats[1] = Q;
    }
    __syncthreads();
    float mean = stats[0] * (1.f / 256.f);
    float var = stats[1] * (1.f / 256.f) - mean * mean;
    float rstd = rsqrtf(var + 1e-5f);
    float n = (s - mean) * rstd * __ldg(gg + tid) + __ldg(bn + tid);
    float4 w2 = *(const float4*)(W2 + tid * 4);
    float p[4] = {n * w2.x, n * w2.y, n * w2.z, n * w2.w};
    for (int j = 0; j < 4; j++) {
        red[tid] = p[j];
        __syncthreads();
        for (int st = 128; st > 0; st >>= 1) {
            if (tid < st) red[tid] += red[tid + st];
            __syncthreads();
        }
        if (tid == 0) out[g * 4 + j] = red[0] + __ldg(b2 + j);
        __syncthreads();
    }
}

// ---------------- launch ----------------
extern "C" void kernel_launch(void* const* d_in, const int* in_sizes, int n_in,
                              void* d_out, int out_size) {
    const float* x      = (const float*)d_in[0];
    const int*   ei     = (const int*)d_in[1];
    const int*   ptr    = (const int*)d_in[3];
    const float* Wl0    = (const float*)d_in[4];
    const float* bl0    = (const float*)d_in[5];
    const float* Wr0    = (const float*)d_in[6];
    const float* Wl     = (const float*)d_in[7];
    const float* bl     = (const float*)d_in[8];
    const float* Wr     = (const float*)d_in[9];
    const float* Wres   = (const float*)d_in[10];
    const float* bres   = (const float*)d_in[11];
    const float* ln_g   = (const float*)d_in[12];
    const float* ln_b   = (const float*)d_in[13];
    const float* mlp_W1 = (const float*)d_in[14];
    const float* mlp_b1 = (const float*)d_in[15];
    const float* mlp_g  = (const float*)d_in[16];
    const float* mlp_bn = (const float*)d_in[17];
    const float* mlp_W2 = (const float*)d_in[18];
    const float* mlp_b2 = (const float*)d_in[19];
    const float* ro_W1  = (const float*)d_in[20];
    const float* ro_b1  = (const float*)d_in[21];
    const float* ro_g   = (const float*)d_in[22];
    const float* ro_bn  = (const float*)d_in[23];
    const float* ro_W2  = (const float*)d_in[24];
    const float* ro_b2  = (const float*)d_in[25];
    float* out = (float*)d_out;

    void* p;
    cudaGetSymbolAddress(&p, g_deg);    int* deg = (int*)p;
    cudaGetSymbolAddress(&p, g_incl);   int* incl = (int*)p;
    cudaGetSymbolAddress(&p, g_rowptr); int* rowptr = (int*)p;
    cudaGetSymbolAddress(&p, g_cur);    int* cur = (int*)p;
    cudaGetSymbolAddress(&p, g_bsums);  int* bsums = (int*)p;
    cudaGetSymbolAddress(&p, g_csr);    int* csr = (int*)p;
    cudaGetSymbolAddress(&p, g_hA);     float* hA = (float*)p;
    cudaGetSymbolAddress(&p, g_hB);     float* hB = (float*)p;
    cudaGetSymbolAddress(&p, g_agg);    float* agg = (float*)p;
    cudaGetSymbolAddress(&p, g_obuf);   float* obuf = (float*)p;

    cudaFuncSetAttribute(sage_gemm_kernel, cudaFuncAttributeMaxDynamicSharedMemorySize, SG_SMEM);
    cudaFuncSetAttribute(mlp_kernel, cudaFuncAttributeMaxDynamicSharedMemorySize, MLP_SMEM);

    zero_deg_kernel<<<(NN + 255) / 256, 256>>>(deg);
    hist_kernel<<<(NE + 255) / 256, 256>>>(ei, deg);
    scan1_kernel<<<(NN + 1023) / 1024, 1024>>>(deg, incl, bsums);
    scan2_kernel<<<1, 128>>>(bsums, (NN + 1023) / 1024);
    scan3_kernel<<<(NN + 255) / 256, 256>>>(incl, deg, bsums, rowptr, cur);
    scatter_kernel<<<(NE + 255) / 256, 256>>>(ei, cur, csr);

    layer0_kernel<<<(NN + 3) / 4, 256>>>(x, rowptr, csr, Wl0, bl0, Wr0, Wres, bres,
                                         ln_g, ln_b, hA);

    const float* hin = hA;
    float* hout = hB;
    for (int i = 0; i < 3; i++) {
        agg_kernel<<<(NN + 3) / 4, 256>>>(hin, rowptr, csr, agg);
        sage_gemm_kernel<<<296, 256, SG_SMEM>>>(agg, hin, Wl + i * 128 * 64, bl + i * 64,
                                                Wr + i * 64 * 64, ln_g + (i + 1) * 64,
                                                ln_b + (i + 1) * 64, hout);
        const float* tmp = hin;
        hin = hout;
        hout = (float*)tmp;
    }
    // hin == hB (final sage output), hout == hA
    mlp_kernel<<<148, 256, MLP_SMEM>>>(hin, mlp_W1, mlp_b1, mlp_g, mlp_bn, mlp_W2, mlp_b2, hout);
    pool_kernel<<<NG, 256>>>(hout, x, ptr, obuf);
    readout_kernel<<<NG, 256>>>(obuf, ro_W1, ro_b1, ro_g, ro_bn, ro_W2, ro_b2, out);
}

// round 5
// speedup vs baseline: 1.2382x; 1.0477x over previous
#include <cuda_runtime.h>
#include <cuda_bf16.h>
#include <math.h>
#include <stdint.h>

#define NN 100000
#define NE 1600000
#define NG 200
#define HID 64

// ---------------- scratch (static device globals; no allocation) ----------------
__device__ int   g_deg[NN];
__device__ int   g_incl[NN];
__device__ int   g_rowptr[NN + 1];
__device__ int   g_cur[NN];
__device__ int   g_bsums[256];
__device__ int   g_csr[NE];
__device__ float g_hA[NN * HID];
__device__ float g_hB[NN * HID];
__device__ float g_agg[NN * 128];
__device__ float g_obuf[NG * 196];

__device__ __forceinline__ float silu_f(float z) { return z / (1.f + __expf(-z)); }

__device__ __forceinline__ uint32_t smem_u32(const void* p) {
    uint32_t a;
    asm("{ .reg .u64 t; cvta.to.shared.u64 t, %1; cvt.u32.u64 %0, t; }" : "=r"(a) : "l"(p));
    return a;
}

// hi = truncate-to-bf16 (bit mask), lo = x - hi rounded to bf16. err <= 2^-15 rel.
__device__ __forceinline__ void split_pack(float4 f, uint32_t& h01, uint32_t& h23,
                                           uint32_t& l01, uint32_t& l23) {
    uint32_t x0 = __float_as_uint(f.x), x1 = __float_as_uint(f.y);
    uint32_t x2 = __float_as_uint(f.z), x3 = __float_as_uint(f.w);
    h01 = __byte_perm(x0, x1, 0x7632);
    h23 = __byte_perm(x2, x3, 0x7632);
    float l0 = f.x - __uint_as_float(x0 & 0xFFFF0000u);
    float l1 = f.y - __uint_as_float(x1 & 0xFFFF0000u);
    float l2 = f.z - __uint_as_float(x2 & 0xFFFF0000u);
    float l3 = f.w - __uint_as_float(x3 & 0xFFFF0000u);
    asm("cvt.rn.bf16x2.f32 %0, %1, %2;" : "=r"(l01) : "f"(l1), "f"(l0));
    asm("cvt.rn.bf16x2.f32 %0, %1, %2;" : "=r"(l23) : "f"(l3), "f"(l2));
}

__device__ __forceinline__ void ldsm4(uint32_t* r, uint32_t addr) {
    asm volatile("ldmatrix.sync.aligned.m8n8.x4.shared.b16 {%0,%1,%2,%3}, [%4];"
                 : "=r"(r[0]), "=r"(r[1]), "=r"(r[2]), "=r"(r[3]) : "r"(addr));
}

__device__ __forceinline__ void mma16816(float* c, const uint32_t* a, uint32_t b0, uint32_t b1) {
    asm volatile(
        "mma.sync.aligned.m16n8k16.row.col.f32.bf16.bf16.f32 "
        "{%0,%1,%2,%3}, {%4,%5,%6,%7}, {%8,%9}, {%0,%1,%2,%3};"
        : "+f"(c[0]), "+f"(c[1]), "+f"(c[2]), "+f"(c[3])
        : "r"(a[0]), "r"(a[1]), "r"(a[2]), "r"(a[3]), "r"(b0), "r"(b1));
}

// ---------------- CSR build ----------------
__global__ void zero_deg_kernel(int* deg) {
    int i = blockIdx.x * blockDim.x + threadIdx.x;
    if (i < NN) deg[i] = 0;
}

__global__ void hist_kernel(const int* __restrict__ ei, int* __restrict__ deg) {
    int e = blockIdx.x * blockDim.x + threadIdx.x;
    if (e < NE) atomicAdd(&deg[ei[NE + e]], 1);
}

__global__ void scan1_kernel(const int* __restrict__ deg, int* __restrict__ incl,
                             int* __restrict__ bsums) {
    __shared__ int s[1024];
    int tid = threadIdx.x;
    int i = blockIdx.x * 1024 + tid;
    s[tid] = (i < NN) ? deg[i] : 0;
    __syncthreads();
    for (int off = 1; off < 1024; off <<= 1) {
        int v = (tid >= off) ? s[tid - off] : 0;
        __syncthreads();
        s[tid] += v;
        __syncthreads();
    }
    if (i < NN) incl[i] = s[tid];
    if (tid == 1023) bsums[blockIdx.x] = s[1023];
}

__global__ void scan2_kernel(int* bsums, int nb) {
    __shared__ int s[128];
    int tid = threadIdx.x;
    int v = (tid < nb) ? bsums[tid] : 0;
    s[tid] = v;
    __syncthreads();
    for (int off = 1; off < 128; off <<= 1) {
        int t = (tid >= off) ? s[tid - off] : 0;
        __syncthreads();
        s[tid] += t;
        __syncthreads();
    }
    if (tid < nb) bsums[tid] = s[tid] - v;  // exclusive
}

__global__ void scan3_kernel(const int* __restrict__ incl, const int* __restrict__ deg,
                             const int* __restrict__ bsums, int* __restrict__ rowptr,
                             int* __restrict__ cur) {
    int i = blockIdx.x * blockDim.x + threadIdx.x;
    if (i < NN) {
        int val = incl[i] + bsums[i >> 10];
        rowptr[i + 1] = val;
        cur[i] = val - deg[i];
    }
    if (i == 0) rowptr[0] = 0;
}

__global__ void scatter_kernel(const int* __restrict__ ei, int* __restrict__ cur,
                               int* __restrict__ csr) {
    int e = blockIdx.x * blockDim.x + threadIdx.x;
    if (e < NE) {
        int d = ei[NE + e];
        int p = atomicAdd(&cur[d], 1);
        csr[p] = ei[e];
    }
}

// ---------------- layer 0 (IN=4): fully fused sage + LN + x_res + silu ----------------
__global__ __launch_bounds__(256) void layer0_kernel(
    const float* __restrict__ x, const int* __restrict__ rowptr, const int* __restrict__ csr,
    const float* __restrict__ Wl0, const float* __restrict__ bl0, const float* __restrict__ Wr0,
    const float* __restrict__ Wres, const float* __restrict__ bres,
    const float* __restrict__ lng, const float* __restrict__ lnb, float* __restrict__ hout) {
    int tid = threadIdx.x;
    int grp = tid >> 6;
    int l = tid & 63;
    int v = blockIdx.x * 4 + grp;
    bool valid = (v < NN);
    __shared__ float sMx[4][64], sSm[4][64], sAgg[4][8], sX[4][4], sP[4][2][2];
    int start = 0, end = 0;
    if (valid) { start = rowptr[v]; end = rowptr[v + 1]; }
    if (valid && l < 4) sX[grp][l] = x[v * 4 + l];
    int es = l >> 2, dim = l & 3;
    float mx = -INFINITY, sm = 0.f;
    for (int e = start + es; e < end; e += 16) {
        int s = csr[e];
        float val = x[s * 4 + dim];
        mx = fmaxf(mx, val);
        sm += val;
    }
    sMx[grp][l] = mx; sSm[grp][l] = sm;
    __syncthreads();
    if (l < 8) {
        int dd = l & 3;
        int deg = end - start;
        if (l < 4) {
            float m = -INFINITY;
            #pragma unroll
            for (int j = 0; j < 16; j++) m = fmaxf(m, sMx[grp][j * 4 + dd]);
            sAgg[grp][dd] = (deg > 0) ? m : 0.f;
        } else {
            float s2 = 0.f;
            #pragma unroll
            for (int j = 0; j < 16; j++) s2 += sSm[grp][j * 4 + dd];
            sAgg[grp][4 + dd] = s2 / (float)(deg > 0 ? deg : 1);
        }
    }
    __syncthreads();
    float acc = __ldg(bl0 + l);
    #pragma unroll
    for (int k = 0; k < 8; k++) acc += sAgg[grp][k] * __ldg(Wl0 + k * 64 + l);
    float xres = __ldg(bres + l);
    #pragma unroll
    for (int k = 0; k < 4; k++) {
        float xv = sX[grp][k];
        acc += xv * __ldg(Wr0 + k * 64 + l);
        xres += xv * __ldg(Wres + k * 64 + l);
    }
    float s1 = acc, q1 = acc * acc;
    #pragma unroll
    for (int m2 = 1; m2 < 32; m2 <<= 1) {
        s1 += __shfl_xor_sync(0xffffffffu, s1, m2);
        q1 += __shfl_xor_sync(0xffffffffu, q1, m2);
    }
    int w = (tid >> 5) & 1;
    if ((tid & 31) == 0) { sP[grp][w][0] = s1; sP[grp][w][1] = q1; }
    __syncthreads();
    float S = sP[grp][0][0] + sP[grp][1][0];
    float Q = sP[grp][0][1] + sP[grp][1][1];
    float mean = S * (1.f / 64.f);
    float var = Q * (1.f / 64.f) - mean * mean;
    float rstd = rsqrtf(var + 1e-5f);
    float z = (acc - mean) * rstd * __ldg(lng + l) + __ldg(lnb + l) + xres;
    if (valid) hout[v * 64 + l] = silu_f(z);
}

// ---------------- aggregation (hidden layers): WIDE grid, 8-unrolled gather ---------
__global__ __launch_bounds__(256) void agg_kernel(const float* __restrict__ hin,
                                                  const int* __restrict__ rowptr,
                                                  const int* __restrict__ csr,
                                                  float* __restrict__ aggout) {
    int tid = threadIdx.x;
    int grp = tid >> 6;
    int l = tid & 63;
    int v = blockIdx.x * 4 + grp;
    if (v >= NN) return;
    int start = rowptr[v], end = rowptr[v + 1];
    float mx = -INFINITY, sm = 0.f;
    int e = start;
    for (; e + 8 <= end; e += 8) {
        int i0 = csr[e], i1 = csr[e + 1], i2 = csr[e + 2], i3 = csr[e + 3];
        int i4 = csr[e + 4], i5 = csr[e + 5], i6 = csr[e + 6], i7 = csr[e + 7];
        float v0 = hin[i0 * 64 + l], v1 = hin[i1 * 64 + l];
        float v2 = hin[i2 * 64 + l], v3 = hin[i3 * 64 + l];
        float v4 = hin[i4 * 64 + l], v5 = hin[i5 * 64 + l];
        float v6 = hin[i6 * 64 + l], v7 = hin[i7 * 64 + l];
        mx = fmaxf(mx, fmaxf(fmaxf(v0, v1), fmaxf(v2, v3)));
        mx = fmaxf(mx, fmaxf(fmaxf(v4, v5), fmaxf(v6, v7)));
        sm += ((v0 + v1) + (v2 + v3)) + ((v4 + v5) + (v6 + v7));
    }
    for (; e < end; e++) {
        float vv = hin[csr[e] * 64 + l];
        mx = fmaxf(mx, vv);
        sm += vv;
    }
    int deg = end - start;
    aggout[v * 128 + l] = (deg > 0) ? mx : 0.f;
    aggout[v * 128 + 64 + l] = sm / (float)(deg > 0 ? deg : 1);
}

// ---------------- sage hidden layer via mma.sync bf16 hi/lo (fp32 accum) -------------
// Tile M=128, N=64, K=192. A = [agg(128) | h(64)] rows x k; B[n][k] = W[k][n].
// SMEM: Ahi/Alo 128x(192+8pad) bf16, Bhi/Blo 64x200 bf16, + 128x2 float2 LN partials.
#define MMA_SMEM 155648
__global__ __launch_bounds__(256) void sage_mma_kernel(
    const float* __restrict__ agg, const float* __restrict__ hin,
    const float* __restrict__ Wl, const float* __restrict__ bl, const float* __restrict__ Wr,
    const float* __restrict__ lng, const float* __restrict__ lnb, float* __restrict__ hout) {
    extern __shared__ char smem[];
    uint32_t sbase = smem_u32(smem);
    const uint32_t SAH = sbase, SAL = sbase + 51200;
    const uint32_t SBH = sbase + 102400, SBL = sbase + 128000;
    float2* sRed = (float2*)(smem + 153600);  // [128][2]
    int tid = threadIdx.x;
    int base = blockIdx.x * 128;

    // ---- A panel: convert fp32 -> bf16 hi/lo, row stride 200 bf16 (400 B)
    {
        int row = tid >> 1, half = tid & 1;
        int grow = base + row;
        bool valid = grow < NN;
        const float* ar = agg + (long)grow * 128;
        const float* hr = hin + (long)grow * 64;
        uint32_t dh = SAH + row * 400 + half * 192;
        uint32_t dl = SAL + row * 400 + half * 192;
        #pragma unroll
        for (int it = 0; it < 24; it++) {
            int c = half * 96 + it * 4;
            float4 f = make_float4(0.f, 0.f, 0.f, 0.f);
            if (valid) f = (c < 128) ? *(const float4*)(ar + c) : *(const float4*)(hr + c - 128);
            uint32_t h01, h23, l01, l23;
            split_pack(f, h01, h23, l01, l23);
            asm volatile("st.shared.v2.u32 [%0], {%1,%2};" :: "r"(dh + it * 8), "r"(h01), "r"(h23));
            asm volatile("st.shared.v2.u32 [%0], {%1,%2};" :: "r"(dl + it * 8), "r"(l01), "r"(l23));
        }
    }
    // ---- B panel: B[n][k] = W[k][n]
    {
        int n = tid >> 2, q = tid & 3;
        uint32_t dh = SBH + n * 400 + q * 96;
        uint32_t dl = SBL + n * 400 + q * 96;
        #pragma unroll
        for (int it = 0; it < 12; it++) {
            int k = q * 48 + it * 4;
            float4 f;
            f.x = (k + 0 < 128) ? __ldg(Wl + (k + 0) * 64 + n) : __ldg(Wr + (k - 128) * 64 + n);
            f.y = (k + 1 < 128) ? __ldg(Wl + (k + 1) * 64 + n) : __ldg(Wr + (k - 127) * 64 + n);
            f.z = (k + 2 < 128) ? __ldg(Wl + (k + 2) * 64 + n) : __ldg(Wr + (k - 126) * 64 + n);
            f.w = (k + 3 < 128) ? __ldg(Wl + (k + 3) * 64 + n) : __ldg(Wr + (k - 125) * 64 + n);
            uint32_t h01, h23, l01, l23;
            split_pack(f, h01, h23, l01, l23);
            asm volatile("st.shared.v2.u32 [%0], {%1,%2};" :: "r"(dh + it * 8), "r"(h01), "r"(h23));
            asm volatile("st.shared.v2.u32 [%0], {%1,%2};" :: "r"(dl + it * 8), "r"(l01), "r"(l23));
        }
    }
    __syncthreads();

    // ---- MMA mainloop: warp grid 4(m) x 2(n); each warp 32 rows x 32 cols
    int w = tid >> 5, lane = tid & 31;
    int mblk = (w & 3) * 32, nblk = (w >> 2) * 32;
    float acc[2][4][4];
    #pragma unroll
    for (int a = 0; a < 2; a++)
        #pragma unroll
        for (int b = 0; b < 4; b++)
            #pragma unroll
            for (int c = 0; c < 4; c++) acc[a][b][c] = 0.f;

    uint32_t aRel = (uint32_t)((mblk + (lane & 15)) * 400 + (((lane >> 4) & 1) * 8) * 2);
    uint32_t bRel = (uint32_t)((nblk + ((lane >> 4) & 1) * 8 + (lane & 7)) * 400 +
                               (((lane >> 3) & 1) * 8) * 2);
    #pragma unroll
    for (int s = 0; s < 12; s++) {
        uint32_t ko = (uint32_t)(s * 32);
        uint32_t ah0[4], ah1[4], al0[4], al1[4];
        ldsm4(ah0, SAH + aRel + ko);
        ldsm4(ah1, SAH + aRel + 6400 + ko);
        ldsm4(al0, SAL + aRel + ko);
        ldsm4(al1, SAL + aRel + 6400 + ko);
        uint32_t bh0[4], bh1[4], bL0[4], bL1[4];
        ldsm4(bh0, SBH + bRel + ko);
        ldsm4(bh1, SBH + bRel + 6400 + ko);
        ldsm4(bL0, SBL + bRel + ko);
        ldsm4(bL1, SBL + bRel + 6400 + ko);
        #pragma unroll
        for (int nt = 0; nt < 4; nt++) {
            uint32_t bhx0 = (nt < 2) ? bh0[(nt & 1) * 2] : bh1[(nt & 1) * 2];
            uint32_t bhx1 = (nt < 2) ? bh0[(nt & 1) * 2 + 1] : bh1[(nt & 1) * 2 + 1];
            uint32_t blx0 = (nt < 2) ? bL0[(nt & 1) * 2] : bL1[(nt & 1) * 2];
            uint32_t blx1 = (nt < 2) ? bL0[(nt & 1) * 2 + 1] : bL1[(nt & 1) * 2 + 1];
            mma16816(acc[0][nt], ah0, bhx0, bhx1);
            mma16816(acc[0][nt], ah0, blx0, blx1);
            mma16816(acc[0][nt], al0, bhx0, bhx1);
            mma16816(acc[1][nt], ah1, bhx0, bhx1);
            mma16816(acc[1][nt], ah1, blx0, blx1);
            mma16816(acc[1][nt], al1, bhx0, bhx1);
        }
    }

    // ---- epilogue: bias, LN (cross-warp via sRed), residual, silu
    int c0 = nblk + (lane & 3) * 2;
    float2 blv[4];
    #pragma unroll
    for (int nt = 0; nt < 4; nt++) blv[nt] = *(const float2*)(bl + c0 + nt * 8);
    #pragma unroll
    for (int mt = 0; mt < 2; mt++)
        #pragma unroll
        for (int nt = 0; nt < 4; nt++) {
            acc[mt][nt][0] += blv[nt].x; acc[mt][nt][1] += blv[nt].y;
            acc[mt][nt][2] += blv[nt].x; acc[mt][nt][3] += blv[nt].y;
        }
    int wn = w >> 2;
    #pragma unroll
    for (int mt = 0; mt < 2; mt++) {
        #pragma unroll
        for (int h = 0; h < 2; h++) {
            float s = 0.f, q = 0.f;
            #pragma unroll
            for (int nt = 0; nt < 4; nt++) {
                float v0 = acc[mt][nt][h * 2], v1 = acc[mt][nt][h * 2 + 1];
                s += v0 + v1;
                q += v0 * v0 + v1 * v1;
            }
            s += __shfl_xor_sync(0xffffffffu, s, 1);
            q += __shfl_xor_sync(0xffffffffu, q, 1);
            s += __shfl_xor_sync(0xffffffffu, s, 2);
            q += __shfl_xor_sync(0xffffffffu, q, 2);
            if ((lane & 3) == 0) {
                int r = mblk + mt * 16 + h * 8 + (lane >> 2);
                sRed[r * 2 + wn] = make_float2(s, q);
            }
        }
    }
    __syncthreads();
    float2 gv[4], bbv[4];
    #pragma unroll
    for (int nt = 0; nt < 4; nt++) {
        gv[nt] = *(const float2*)(lng + c0 + nt * 8);
        bbv[nt] = *(const float2*)(lnb + c0 + nt * 8);
    }
    #pragma unroll
    for (int mt = 0; mt < 2; mt++) {
        #pragma unroll
        for (int h = 0; h < 2; h++) {
            int r = mblk + mt * 16 + h * 8 + (lane >> 2);
            float2 p0 = sRed[r * 2 + 0], p1 = sRed[r * 2 + 1];
            float S = p0.x + p1.x, Q = p0.y + p1.y;
            float mean = S * (1.f / 64.f);
            float var = Q * (1.f / 64.f) - mean * mean;
            float rstd = rsqrtf(var + 1e-5f);
            int grow = base + r;
            if (grow < NN) {
                float* orow = hout + (long)grow * 64;
                const float* rrow = hin + (long)grow * 64;
                #pragma unroll
                for (int nt = 0; nt < 4; nt++) {
                    float2 res = *(const float2*)(rrow + c0 + nt * 8);
                    float v0 = acc[mt][nt][h * 2], v1 = acc[mt][nt][h * 2 + 1];
                    float2 o;
                    o.x = silu_f((v0 - mean) * rstd * gv[nt].x + bbv[nt].x + res.x);
                    o.y = silu_f((v1 - mean) * rstd * gv[nt].y + bbv[nt].y + res.y);
                    *(float2*)(orow + c0 + nt * 8) = o;
                }
            }
        }
    }
}

// ---------------- node MLP: silu(h@W1+b1) -> LN -> @W2+b2, fused ----------------
#define MLP_SMEM ((64 * 256 + 256 * 64 + 32 * 68 + 32 * 260 + 128) * 4)
__global__ __launch_bounds__(256) void mlp_kernel(
    const float* __restrict__ hin, const float* __restrict__ W1, const float* __restrict__ b1,
    const float* __restrict__ gg, const float* __restrict__ bn,
    const float* __restrict__ W2, const float* __restrict__ b2, float* __restrict__ hout) {
    extern __shared__ float smemf[];
    float* sW1 = smemf;              // 64*256
    float* sW2 = sW1 + 64 * 256;     // 256*64
    float* sA = sW2 + 256 * 64;      // 32 x 68
    float* sT = sA + 32 * 68;        // 32 x 260
    float* sRed = sT + 32 * 260;     // 8 warps * 16
    int tid = threadIdx.x;
    for (int i = tid; i < 64 * 256 / 4; i += 256) ((float4*)sW1)[i] = ((const float4*)W1)[i];
    for (int i = tid; i < 256 * 64 / 4; i += 256) ((float4*)sW2)[i] = ((const float4*)W2)[i];
    int ty = tid >> 6, tx = tid & 63;
    int ry = tid >> 4, cx = tid & 15;
    int warp = tid >> 5;
    float4 b1v = *(const float4*)(b1 + tx * 4);
    float4 gv = *(const float4*)(gg + tx * 4);
    float4 bnv = *(const float4*)(bn + tx * 4);
    float4 b2v = *(const float4*)(b2 + cx * 4);
    const int NT = NN / 32;  // 3125 exact
    for (int t = blockIdx.x; t < NT; t += gridDim.x) {
        __syncthreads();
        int base = t * 32;
        for (int i = tid; i < 32 * 16; i += 256) {
            int r = i >> 4, c = i & 15;
            ((float4*)(sA + r * 68))[c] = ((const float4*)(hin + (long)(base + r) * 64))[c];
        }
        __syncthreads();
        float acc[8][4];
        #pragma unroll
        for (int i = 0; i < 8; i++)
            #pragma unroll
            for (int j = 0; j < 4; j++) acc[i][j] = 0.f;
        #pragma unroll 2
        for (int k = 0; k < 64; k += 4) {
            float4 w0 = *(float4*)(sW1 + (k + 0) * 256 + tx * 4);
            float4 w1 = *(float4*)(sW1 + (k + 1) * 256 + tx * 4);
            float4 w2 = *(float4*)(sW1 + (k + 2) * 256 + tx * 4);
            float4 w3 = *(float4*)(sW1 + (k + 3) * 256 + tx * 4);
            #pragma unroll
            for (int i = 0; i < 8; i++) {
                float4 a = *(float4*)(sA + (ty * 8 + i) * 68 + k);
                acc[i][0] += a.x * w0.x; acc[i][1] += a.x * w0.y;
                acc[i][2] += a.x * w0.z; acc[i][3] += a.x * w0.w;
                acc[i][0] += a.y * w1.x; acc[i][1] += a.y * w1.y;
                acc[i][2] += a.y * w1.z; acc[i][3] += a.y * w1.w;
                acc[i][0] += a.z * w2.x; acc[i][1] += a.z * w2.y;
                acc[i][2] += a.z * w2.z; acc[i][3] += a.z * w2.w;
                acc[i][0] += a.w * w3.x; acc[i][1] += a.w * w3.y;
                acc[i][2] += a.w * w3.z; acc[i][3] += a.w * w3.w;
            }
        }
        float ls[8], lq[8];
        #pragma unroll
        for (int i = 0; i < 8; i++) {
            acc[i][0] = silu_f(acc[i][0] + b1v.x);
            acc[i][1] = silu_f(acc[i][1] + b1v.y);
            acc[i][2] = silu_f(acc[i][2] + b1v.z);
            acc[i][3] = silu_f(acc[i][3] + b1v.w);
            ls[i] = (acc[i][0] + acc[i][1]) + (acc[i][2] + acc[i][3]);
            lq[i] = acc[i][0] * acc[i][0] + acc[i][1] * acc[i][1] +
                    acc[i][2] * acc[i][2] + acc[i][3] * acc[i][3];
        }
        #pragma unroll
        for (int i = 0; i < 8; i++) {
            float s = ls[i], q = lq[i];
            #pragma unroll
            for (int m2 = 1; m2 < 32; m2 <<= 1) {
                s += __shfl_xor_sync(0xffffffffu, s, m2);
                q += __shfl_xor_sync(0xffffffffu, q, m2);
            }
            ls[i] = s; lq[i] = q;
        }
        if ((tid & 31) == 0) {
            #pragma unroll
            for (int i = 0; i < 8; i++) {
                sRed[warp * 16 + i * 2] = ls[i];
                sRed[warp * 16 + i * 2 + 1] = lq[i];
            }
        }
        __syncthreads();
        int wb = (ty * 2) * 16;
        #pragma unroll
        for (int i = 0; i < 8; i++) {
            float S = sRed[wb + i * 2] + sRed[wb + 16 + i * 2];
            float Q = sRed[wb + i * 2 + 1] + sRed[wb + 16 + i * 2 + 1];
            float mean = S * (1.f / 256.f);
            float var = Q * (1.f / 256.f) - mean * mean;
            float rstd = rsqrtf(var + 1e-5f);
            float4 n;
            n.x = (acc[i][0] - mean) * rstd * gv.x + bnv.x;
            n.y = (acc[i][1] - mean) * rstd * gv.y + bnv.y;
            n.z = (acc[i][2] - mean) * rstd * gv.z + bnv.z;
            n.w = (acc[i][3] - mean) * rstd * gv.w + bnv.w;
            *(float4*)(sT + (ty * 8 + i) * 260 + tx * 4) = n;
        }
        __syncthreads();
        float a2[2][4];
        #pragma unroll
        for (int i = 0; i < 2; i++)
            #pragma unroll
            for (int j = 0; j < 4; j++) a2[i][j] = 0.f;
        #pragma unroll 4
        for (int k = 0; k < 256; k += 4) {
            float4 w0 = *(float4*)(sW2 + (k + 0) * 64 + cx * 4);
            float4 w1 = *(float4*)(sW2 + (k + 1) * 64 + cx * 4);
            float4 w2 = *(float4*)(sW2 + (k + 2) * 64 + cx * 4);
            float4 w3 = *(float4*)(sW2 + (k + 3) * 64 + cx * 4);
            float4 a0 = *(float4*)(sT + (ry * 2) * 260 + k);
            float4 a1 = *(float4*)(sT + (ry * 2 + 1) * 260 + k);
            a2[0][0] += a0.x * w0.x; a2[0][1] += a0.x * w0.y; a2[0][2] += a0.x * w0.z; a2[0][3] += a0.x * w0.w;
            a2[0][0] += a0.y * w1.x; a2[0][1] += a0.y * w1.y; a2[0][2] += a0.y * w1.z; a2[0][3] += a0.y * w1.w;
            a2[0][0] += a0.z * w2.x; a2[0][1] += a0.z * w2.y; a2[0][2] += a0.z * w2.z; a2[0][3] += a0.z * w2.w;
            a2[0][0] += a0.w * w3.x; a2[0][1] += a0.w * w3.y; a2[0][2] += a0.w * w3.z; a2[0][3] += a0.w * w3.w;
            a2[1][0] += a1.x * w0.x; a2[1][1] += a1.x * w0.y; a2[1][2] += a1.x * w0.z; a2[1][3] += a1.x * w0.w;
            a2[1][0] += a1.y * w1.x; a2[1][1] += a1.y * w1.y; a2[1][2] += a1.y * w1.z; a2[1][3] += a1.y * w1.w;
            a2[1][0] += a1.z * w2.x; a2[1][1] += a1.z * w2.y; a2[1][2] += a1.z * w2.z; a2[1][3] += a1.z * w2.w;
            a2[1][0] += a1.w * w3.x; a2[1][1] += a1.w * w3.y; a2[1][2] += a1.w * w3.z; a2[1][3] += a1.w * w3.w;
        }
        int r0 = base + ry * 2;
        float4 o0 = make_float4(a2[0][0] + b2v.x, a2[0][1] + b2v.y, a2[0][2] + b2v.z, a2[0][3] + b2v.w);
        float4 o1 = make_float4(a2[1][0] + b2v.x, a2[1][1] + b2v.y, a2[1][2] + b2v.z, a2[1][3] + b2v.w);
        *(float4*)(hout + (long)r0 * 64 + cx * 4) = o0;
        *(float4*)(hout + (long)(r0 + 1) * 64 + cx * 4) = o1;
    }
}

// ---------------- graph pooling: mean | max | sum | root ----------------
__global__ __launch_bounds__(256) void pool_kernel(const float* __restrict__ h,
                                                   const float* __restrict__ x,
                                                   const int* __restrict__ ptr,
                                                   float* __restrict__ o) {
    int g = blockIdx.x;
    int start = ptr[g], end = ptr[g + 1];
    int tid = threadIdx.x;
    int rl = tid >> 6, d = tid & 63;
    float sm = 0.f, mx = -INFINITY;
    for (int r = start + rl; r < end; r += 4) {
        float v = h[(long)r * 64 + d];
        sm += v;
        mx = fmaxf(mx, v);
    }
    __shared__ float sS[4][64], sM[4][64];
    sS[rl][d] = sm; sM[rl][d] = mx;
    __syncthreads();
    if (tid < 64) {
        float s = sS[0][tid] + sS[1][tid] + sS[2][tid] + sS[3][tid];
        float m = fmaxf(fmaxf(sM[0][tid], sM[1][tid]), fmaxf(sM[2][tid], sM[3][tid]));
        int cnt = end - start;
        float mean = s / (float)(cnt > 0 ? cnt : 1);
        if (m == -INFINITY) m = 0.f;
        o[g * 196 + tid] = mean;
        o[g * 196 + 64 + tid] = m;
        o[g * 196 + 128 + tid] = s;
    }
    if (tid < 4) o[g * 196 + 192 + tid] = x[(long)start * 4 + tid];
}

// ---------------- readout: silu(o@W1+b1) -> LN -> @W2+b2 ----------------
__global__ __launch_bounds__(256) void readout_kernel(
    const float* __restrict__ o, const float* __restrict__ W1, const float* __restrict__ b1,
    const float* __restrict__ gg, const float* __restrict__ bn,
    const float* __restrict__ W2, const float* __restrict__ b2, float* __restrict__ out) {
    int g = blockIdx.x;
    int tid = threadIdx.x;
    __shared__ float so[196];
    __shared__ float red[256];
    __shared__ float ws[8][2];
    __shared__ float stats[2];
    if (tid < 196) so[tid] = o[g * 196 + tid];
    __syncthreads();
    float acc = __ldg(b1 + tid);
    #pragma unroll 4
    for (int k = 0; k < 196; k++) acc += so[k] * __ldg(W1 + k * 256 + tid);
    float s = silu_f(acc);
    float ls = s, lq = s * s;
    #pragma unroll
    for (int m2 = 1; m2 < 32; m2 <<= 1) {
        ls += __shfl_xor_sync(0xffffffffu, ls, m2);
        lq += __shfl_xor_sync(0xffffffffu, lq, m2);
    }
    int w = tid >> 5;
    if ((tid & 31) == 0) { ws[w][0] = ls; ws[w][1] = lq; }
    __syncthreads();
    if (tid == 0) {
        float S = 0.f, Q = 0.f;
        for (int i = 0; i < 8; i++) { S += ws[i][0]; Q += ws[i][1]; }
        stats[0] = S; stats[1] = Q;
    }
    __syncthreads();
    float mean = stats[0] * (1.f / 256.f);
    float var = stats[1] * (1.f / 256.f) - mean * mean;
    float rstd = rsqrtf(var + 1e-5f);
    float n = (s - mean) * rstd * __ldg(gg + tid) + __ldg(bn + tid);
    float4 w2 = *(const float4*)(W2 + tid * 4);
    float p[4] = {n * w2.x, n * w2.y, n * w2.z, n * w2.w};
    for (int j = 0; j < 4; j++) {
        red[tid] = p[j];
        __syncthreads();
        for (int st = 128; st > 0; st >>= 1) {
            if (tid < st) red[tid] += red[tid + st];
            __syncthreads();
        }
        if (tid == 0) out[g * 4 + j] = red[0] + __ldg(b2 + j);
        __syncthreads();
    }
}

// ---------------- launch ----------------
extern "C" void kernel_launch(void* const* d_in, const int* in_sizes, int n_in,
                              void* d_out, int out_size) {
    const float* x      = (const float*)d_in[0];
    const int*   ei     = (const int*)d_in[1];
    const int*   ptr    = (const int*)d_in[3];
    const float* Wl0    = (const float*)d_in[4];
    const float* bl0    = (const float*)d_in[5];
    const float* Wr0    = (const float*)d_in[6];
    const float* Wl     = (const float*)d_in[7];
    const float* bl     = (const float*)d_in[8];
    const float* Wr     = (const float*)d_in[9];
    const float* Wres   = (const float*)d_in[10];
    const float* bres   = (const float*)d_in[11];
    const float* ln_g   = (const float*)d_in[12];
    const float* ln_b   = (const float*)d_in[13];
    const float* mlp_W1 = (const float*)d_in[14];
    const float* mlp_b1 = (const float*)d_in[15];
    const float* mlp_g  = (const float*)d_in[16];
    const float* mlp_bn = (const float*)d_in[17];
    const float* mlp_W2 = (const float*)d_in[18];
    const float* mlp_b2 = (const float*)d_in[19];
    const float* ro_W1  = (const float*)d_in[20];
    const float* ro_b1  = (const float*)d_in[21];
    const float* ro_g   = (const float*)d_in[22];
    const float* ro_bn  = (const float*)d_in[23];
    const float* ro_W2  = (const float*)d_in[24];
    const float* ro_b2  = (const float*)d_in[25];
    float* out = (float*)d_out;

    void* p;
    cudaGetSymbolAddress(&p, g_deg);    int* deg = (int*)p;
    cudaGetSymbolAddress(&p, g_incl);   int* incl = (int*)p;
    cudaGetSymbolAddress(&p, g_rowptr); int* rowptr = (int*)p;
    cudaGetSymbolAddress(&p, g_cur);    int* cur = (int*)p;
    cudaGetSymbolAddress(&p, g_bsums);  int* bsums = (int*)p;
    cudaGetSymbolAddress(&p, g_csr);    int* csr = (int*)p;
    cudaGetSymbolAddress(&p, g_hA);     float* hA = (float*)p;
    cudaGetSymbolAddress(&p, g_hB);     float* hB = (float*)p;
    cudaGetSymbolAddress(&p, g_agg);    float* agg = (float*)p;
    cudaGetSymbolAddress(&p, g_obuf);   float* obuf = (float*)p;

    cudaFuncSetAttribute(sage_mma_kernel, cudaFuncAttributeMaxDynamicSharedMemorySize, MMA_SMEM);
    cudaFuncSetAttribute(mlp_kernel, cudaFuncAttributeMaxDynamicSharedMemorySize, MLP_SMEM);

    zero_deg_kernel<<<(NN + 255) / 256, 256>>>(deg);
    hist_kernel<<<(NE + 255) / 256, 256>>>(ei, deg);
    scan1_kernel<<<(NN + 1023) / 1024, 1024>>>(deg, incl, bsums);
    scan2_kernel<<<1, 128>>>(bsums, (NN + 1023) / 1024);
    scan3_kernel<<<(NN + 255) / 256, 256>>>(incl, deg, bsums, rowptr, cur);
    scatter_kernel<<<(NE + 255) / 256, 256>>>(ei, cur, csr);

    layer0_kernel<<<(NN + 3) / 4, 256>>>(x, rowptr, csr, Wl0, bl0, Wr0, Wres, bres,
                                         ln_g, ln_b, hA);

    const float* hin = hA;
    float* hout = hB;
    const int NTILE = (NN + 127) / 128;  // 782
    for (int i = 0; i < 3; i++) {
        agg_kernel<<<(NN + 3) / 4, 256>>>(hin, rowptr, csr, agg);
        sage_mma_kernel<<<NTILE, 256, MMA_SMEM>>>(agg, hin, Wl + i * 128 * 64, bl + i * 64,
                                                  Wr + i * 64 * 64, ln_g + (i + 1) * 64,
                                                  ln_b + (i + 1) * 64, hout);
        const float* tmp = hin;
        hin = hout;
        hout = (float*)tmp;
    }
    // hin == hB (final sage output), hout == hA
    mlp_kernel<<<148, 256, MLP_SMEM>>>(hin, mlp_W1, mlp_b1, mlp_g, mlp_bn, mlp_W2, mlp_b2, hout);
    pool_kernel<<<NG, 256>>>(hout, x, ptr, obuf);
    readout_kernel<<<NG, 256>>>(obuf, ro_W1, ro_b1, ro_g, ro_bn, ro_W2, ro_b2, out);
}

// round 6
// speedup vs baseline: 1.5200x; 1.2276x over previous
#include <cuda_runtime.h>
#include <cuda_bf16.h>
#include <math.h>
#include <stdint.h>

#define NN 100000
#define NE 1600000
#define NG 200
#define HID 64

// ---------------- scratch (static device globals; no allocation) ----------------
__device__ int   g_deg[NN];
__device__ int   g_incl[NN];
__device__ int   g_rowptr[NN + 1];
__device__ int   g_cur[NN];
__device__ int   g_bsums[256];
__device__ int   g_csr[NE];
__device__ float g_hA[NN * HID];
__device__ float g_hB[NN * HID];
__device__ float g_agg[NN * 128];
__device__ float g_obuf[NG * 196];

__device__ __forceinline__ float silu_f(float z) { return z / (1.f + __expf(-z)); }

__device__ __forceinline__ uint32_t smem_u32(const void* p) {
    uint32_t a;
    asm("{ .reg .u64 t; cvta.to.shared.u64 t, %1; cvt.u32.u64 %0, t; }" : "=r"(a) : "l"(p));
    return a;
}

// hi = truncate-to-bf16 (bit mask), lo = x - hi rounded to bf16. err <= 2^-15 rel.
__device__ __forceinline__ void split_pack(float4 f, uint32_t& h01, uint32_t& h23,
                                           uint32_t& l01, uint32_t& l23) {
    uint32_t x0 = __float_as_uint(f.x), x1 = __float_as_uint(f.y);
    uint32_t x2 = __float_as_uint(f.z), x3 = __float_as_uint(f.w);
    h01 = __byte_perm(x0, x1, 0x7632);
    h23 = __byte_perm(x2, x3, 0x7632);
    float l0 = f.x - __uint_as_float(x0 & 0xFFFF0000u);
    float l1 = f.y - __uint_as_float(x1 & 0xFFFF0000u);
    float l2 = f.z - __uint_as_float(x2 & 0xFFFF0000u);
    float l3 = f.w - __uint_as_float(x3 & 0xFFFF0000u);
    asm("cvt.rn.bf16x2.f32 %0, %1, %2;" : "=r"(l01) : "f"(l1), "f"(l0));
    asm("cvt.rn.bf16x2.f32 %0, %1, %2;" : "=r"(l23) : "f"(l3), "f"(l2));
}

__device__ __forceinline__ void split_pack2(float a, float b, uint32_t& h01, uint32_t& l01) {
    uint32_t x0 = __float_as_uint(a), x1 = __float_as_uint(b);
    h01 = __byte_perm(x0, x1, 0x7632);
    float l0 = a - __uint_as_float(x0 & 0xFFFF0000u);
    float l1 = b - __uint_as_float(x1 & 0xFFFF0000u);
    asm("cvt.rn.bf16x2.f32 %0, %1, %2;" : "=r"(l01) : "f"(l1), "f"(l0));
}

__device__ __forceinline__ void ldsm4(uint32_t* r, uint32_t addr) {
    asm volatile("ldmatrix.sync.aligned.m8n8.x4.shared.b16 {%0,%1,%2,%3}, [%4];"
                 : "=r"(r[0]), "=r"(r[1]), "=r"(r[2]), "=r"(r[3]) : "r"(addr));
}

__device__ __forceinline__ void mma16816(float* c, const uint32_t* a, uint32_t b0, uint32_t b1) {
    asm volatile(
        "mma.sync.aligned.m16n8k16.row.col.f32.bf16.bf16.f32 "
        "{%0,%1,%2,%3}, {%4,%5,%6,%7}, {%8,%9}, {%0,%1,%2,%3};"
        : "+f"(c[0]), "+f"(c[1]), "+f"(c[2]), "+f"(c[3])
        : "r"(a[0]), "r"(a[1]), "r"(a[2]), "r"(a[3]), "r"(b0), "r"(b1));
}

// ---------------- CSR build ----------------
__global__ void zero_deg_kernel(int* deg) {
    int i = blockIdx.x * blockDim.x + threadIdx.x;
    if (i < NN) deg[i] = 0;
}

__global__ void hist_kernel(const int* __restrict__ ei, int* __restrict__ deg) {
    int e = blockIdx.x * blockDim.x + threadIdx.x;
    if (e < NE) atomicAdd(&deg[ei[NE + e]], 1);
}

__global__ void scan1_kernel(const int* __restrict__ deg, int* __restrict__ incl,
                             int* __restrict__ bsums) {
    __shared__ int s[1024];
    int tid = threadIdx.x;
    int i = blockIdx.x * 1024 + tid;
    s[tid] = (i < NN) ? deg[i] : 0;
    __syncthreads();
    for (int off = 1; off < 1024; off <<= 1) {
        int v = (tid >= off) ? s[tid - off] : 0;
        __syncthreads();
        s[tid] += v;
        __syncthreads();
    }
    if (i < NN) incl[i] = s[tid];
    if (tid == 1023) bsums[blockIdx.x] = s[1023];
}

__global__ void scan2_kernel(int* bsums, int nb) {
    __shared__ int s[128];
    int tid = threadIdx.x;
    int v = (tid < nb) ? bsums[tid] : 0;
    s[tid] = v;
    __syncthreads();
    for (int off = 1; off < 128; off <<= 1) {
        int t = (tid >= off) ? s[tid - off] : 0;
        __syncthreads();
        s[tid] += t;
        __syncthreads();
    }
    if (tid < nb) bsums[tid] = s[tid] - v;  // exclusive
}

__global__ void scan3_kernel(const int* __restrict__ incl, const int* __restrict__ deg,
                             const int* __restrict__ bsums, int* __restrict__ rowptr,
                             int* __restrict__ cur) {
    int i = blockIdx.x * blockDim.x + threadIdx.x;
    if (i < NN) {
        int val = incl[i] + bsums[i >> 10];
        rowptr[i + 1] = val;
        cur[i] = val - deg[i];
    }
    if (i == 0) rowptr[0] = 0;
}

__global__ void scatter_kernel(const int* __restrict__ ei, int* __restrict__ cur,
                               int* __restrict__ csr) {
    int e = blockIdx.x * blockDim.x + threadIdx.x;
    if (e < NE) {
        int d = ei[NE + e];
        int p = atomicAdd(&cur[d], 1);
        csr[p] = ei[e];
    }
}

// ---------------- layer 0 (IN=4): fully fused sage + LN + x_res + silu ----------------
__global__ __launch_bounds__(256) void layer0_kernel(
    const float* __restrict__ x, const int* __restrict__ rowptr, const int* __restrict__ csr,
    const float* __restrict__ Wl0, const float* __restrict__ bl0, const float* __restrict__ Wr0,
    const float* __restrict__ Wres, const float* __restrict__ bres,
    const float* __restrict__ lng, const float* __restrict__ lnb, float* __restrict__ hout) {
    int tid = threadIdx.x;
    int grp = tid >> 6;
    int l = tid & 63;
    int v = blockIdx.x * 4 + grp;
    bool valid = (v < NN);
    __shared__ float sMx[4][64], sSm[4][64], sAgg[4][8], sX[4][4], sP[4][2][2];
    int start = 0, end = 0;
    if (valid) { start = rowptr[v]; end = rowptr[v + 1]; }
    if (valid && l < 4) sX[grp][l] = x[v * 4 + l];
    int es = l >> 2, dim = l & 3;
    float mx = -INFINITY, sm = 0.f;
    for (int e = start + es; e < end; e += 16) {
        int s = csr[e];
        float val = x[s * 4 + dim];
        mx = fmaxf(mx, val);
        sm += val;
    }
    sMx[grp][l] = mx; sSm[grp][l] = sm;
    __syncthreads();
    if (l < 8) {
        int dd = l & 3;
        int deg = end - start;
        if (l < 4) {
            float m = -INFINITY;
            #pragma unroll
            for (int j = 0; j < 16; j++) m = fmaxf(m, sMx[grp][j * 4 + dd]);
            sAgg[grp][dd] = (deg > 0) ? m : 0.f;
        } else {
            float s2 = 0.f;
            #pragma unroll
            for (int j = 0; j < 16; j++) s2 += sSm[grp][j * 4 + dd];
            sAgg[grp][4 + dd] = s2 / (float)(deg > 0 ? deg : 1);
        }
    }
    __syncthreads();
    float acc = __ldg(bl0 + l);
    #pragma unroll
    for (int k = 0; k < 8; k++) acc += sAgg[grp][k] * __ldg(Wl0 + k * 64 + l);
    float xres = __ldg(bres + l);
    #pragma unroll
    for (int k = 0; k < 4; k++) {
        float xv = sX[grp][k];
        acc += xv * __ldg(Wr0 + k * 64 + l);
        xres += xv * __ldg(Wres + k * 64 + l);
    }
    float s1 = acc, q1 = acc * acc;
    #pragma unroll
    for (int m2 = 1; m2 < 32; m2 <<= 1) {
        s1 += __shfl_xor_sync(0xffffffffu, s1, m2);
        q1 += __shfl_xor_sync(0xffffffffu, q1, m2);
    }
    int w = (tid >> 5) & 1;
    if ((tid & 31) == 0) { sP[grp][w][0] = s1; sP[grp][w][1] = q1; }
    __syncthreads();
    float S = sP[grp][0][0] + sP[grp][1][0];
    float Q = sP[grp][0][1] + sP[grp][1][1];
    float mean = S * (1.f / 64.f);
    float var = Q * (1.f / 64.f) - mean * mean;
    float rstd = rsqrtf(var + 1e-5f);
    float z = (acc - mean) * rstd * __ldg(lng + l) + __ldg(lnb + l) + xres;
    if (valid) hout[v * 64 + l] = silu_f(z);
}

// ---------------- aggregation (hidden layers): WIDE grid, 8-unrolled gather ---------
__global__ __launch_bounds__(256) void agg_kernel(const float* __restrict__ hin,
                                                  const int* __restrict__ rowptr,
                                                  const int* __restrict__ csr,
                                                  float* __restrict__ aggout) {
    int tid = threadIdx.x;
    int grp = tid >> 6;
    int l = tid & 63;
    int v = blockIdx.x * 4 + grp;
    if (v >= NN) return;
    int start = rowptr[v], end = rowptr[v + 1];
    float mx = -INFINITY, sm = 0.f;
    int e = start;
    for (; e + 8 <= end; e += 8) {
        int i0 = csr[e], i1 = csr[e + 1], i2 = csr[e + 2], i3 = csr[e + 3];
        int i4 = csr[e + 4], i5 = csr[e + 5], i6 = csr[e + 6], i7 = csr[e + 7];
        float v0 = hin[i0 * 64 + l], v1 = hin[i1 * 64 + l];
        float v2 = hin[i2 * 64 + l], v3 = hin[i3 * 64 + l];
        float v4 = hin[i4 * 64 + l], v5 = hin[i5 * 64 + l];
        float v6 = hin[i6 * 64 + l], v7 = hin[i7 * 64 + l];
        mx = fmaxf(mx, fmaxf(fmaxf(v0, v1), fmaxf(v2, v3)));
        mx = fmaxf(mx, fmaxf(fmaxf(v4, v5), fmaxf(v6, v7)));
        sm += ((v0 + v1) + (v2 + v3)) + ((v4 + v5) + (v6 + v7));
    }
    for (; e < end; e++) {
        float vv = hin[csr[e] * 64 + l];
        mx = fmaxf(mx, vv);
        sm += vv;
    }
    int deg = end - start;
    aggout[v * 128 + l] = (deg > 0) ? mx : 0.f;
    aggout[v * 128 + 64 + l] = sm / (float)(deg > 0 ? deg : 1);
}

// ---------------- sage hidden layer via mma.sync bf16 hi/lo (fp32 accum) -------------
#define MMA_SMEM 155648
__global__ __launch_bounds__(256) void sage_mma_kernel(
    const float* __restrict__ agg, const float* __restrict__ hin,
    const float* __restrict__ Wl, const float* __restrict__ bl, const float* __restrict__ Wr,
    const float* __restrict__ lng, const float* __restrict__ lnb, float* __restrict__ hout) {
    extern __shared__ char smem[];
    uint32_t sbase = smem_u32(smem);
    const uint32_t SAH = sbase, SAL = sbase + 51200;
    const uint32_t SBH = sbase + 102400, SBL = sbase + 128000;
    float2* sRed = (float2*)(smem + 153600);  // [128][2]
    int tid = threadIdx.x;
    int base = blockIdx.x * 128;

    {
        int row = tid >> 1, half = tid & 1;
        int grow = base + row;
        bool valid = grow < NN;
        const float* ar = agg + (long)grow * 128;
        const float* hr = hin + (long)grow * 64;
        uint32_t dh = SAH + row * 400 + half * 192;
        uint32_t dl = SAL + row * 400 + half * 192;
        #pragma unroll
        for (int it = 0; it < 24; it++) {
            int c = half * 96 + it * 4;
            float4 f = make_float4(0.f, 0.f, 0.f, 0.f);
            if (valid) f = (c < 128) ? *(const float4*)(ar + c) : *(const float4*)(hr + c - 128);
            uint32_t h01, h23, l01, l23;
            split_pack(f, h01, h23, l01, l23);
            asm volatile("st.shared.v2.u32 [%0], {%1,%2};" :: "r"(dh + it * 8), "r"(h01), "r"(h23));
            asm volatile("st.shared.v2.u32 [%0], {%1,%2};" :: "r"(dl + it * 8), "r"(l01), "r"(l23));
        }
    }
    {
        int n = tid >> 2, q = tid & 3;
        uint32_t dh = SBH + n * 400 + q * 96;
        uint32_t dl = SBL + n * 400 + q * 96;
        #pragma unroll
        for (int it = 0; it < 12; it++) {
            int k = q * 48 + it * 4;
            float4 f;
            f.x = (k + 0 < 128) ? __ldg(Wl + (k + 0) * 64 + n) : __ldg(Wr + (k - 128) * 64 + n);
            f.y = (k + 1 < 128) ? __ldg(Wl + (k + 1) * 64 + n) : __ldg(Wr + (k - 127) * 64 + n);
            f.z = (k + 2 < 128) ? __ldg(Wl + (k + 2) * 64 + n) : __ldg(Wr + (k - 126) * 64 + n);
            f.w = (k + 3 < 128) ? __ldg(Wl + (k + 3) * 64 + n) : __ldg(Wr + (k - 125) * 64 + n);
            uint32_t h01, h23, l01, l23;
            split_pack(f, h01, h23, l01, l23);
            asm volatile("st.shared.v2.u32 [%0], {%1,%2};" :: "r"(dh + it * 8), "r"(h01), "r"(h23));
            asm volatile("st.shared.v2.u32 [%0], {%1,%2};" :: "r"(dl + it * 8), "r"(l01), "r"(l23));
        }
    }
    __syncthreads();

    int w = tid >> 5, lane = tid & 31;
    int mblk = (w & 3) * 32, nblk = (w >> 2) * 32;
    float acc[2][4][4];
    #pragma unroll
    for (int a = 0; a < 2; a++)
        #pragma unroll
        for (int b = 0; b < 4; b++)
            #pragma unroll
            for (int c = 0; c < 4; c++) acc[a][b][c] = 0.f;

    uint32_t aRel = (uint32_t)((mblk + (lane & 15)) * 400 + (((lane >> 4) & 1) * 8) * 2);
    uint32_t bRel = (uint32_t)((nblk + ((lane >> 4) & 1) * 8 + (lane & 7)) * 400 +
                               (((lane >> 3) & 1) * 8) * 2);
    #pragma unroll
    for (int s = 0; s < 12; s++) {
        uint32_t ko = (uint32_t)(s * 32);
        uint32_t ah0[4], ah1[4], al0[4], al1[4];
        ldsm4(ah0, SAH + aRel + ko);
        ldsm4(ah1, SAH + aRel + 6400 + ko);
        ldsm4(al0, SAL + aRel + ko);
        ldsm4(al1, SAL + aRel + 6400 + ko);
        uint32_t bh0[4], bh1[4], bL0[4], bL1[4];
        ldsm4(bh0, SBH + bRel + ko);
        ldsm4(bh1, SBH + bRel + 6400 + ko);
        ldsm4(bL0, SBL + bRel + ko);
        ldsm4(bL1, SBL + bRel + 6400 + ko);
        #pragma unroll
        for (int nt = 0; nt < 4; nt++) {
            uint32_t bhx0 = (nt < 2) ? bh0[(nt & 1) * 2] : bh1[(nt & 1) * 2];
            uint32_t bhx1 = (nt < 2) ? bh0[(nt & 1) * 2 + 1] : bh1[(nt & 1) * 2 + 1];
            uint32_t blx0 = (nt < 2) ? bL0[(nt & 1) * 2] : bL1[(nt & 1) * 2];
            uint32_t blx1 = (nt < 2) ? bL0[(nt & 1) * 2 + 1] : bL1[(nt & 1) * 2 + 1];
            mma16816(acc[0][nt], ah0, bhx0, bhx1);
            mma16816(acc[0][nt], ah0, blx0, blx1);
            mma16816(acc[0][nt], al0, bhx0, bhx1);
            mma16816(acc[1][nt], ah1, bhx0, bhx1);
            mma16816(acc[1][nt], ah1, blx0, blx1);
            mma16816(acc[1][nt], al1, bhx0, bhx1);
        }
    }

    int c0 = nblk + (lane & 3) * 2;
    float2 blv[4];
    #pragma unroll
    for (int nt = 0; nt < 4; nt++) blv[nt] = *(const float2*)(bl + c0 + nt * 8);
    #pragma unroll
    for (int mt = 0; mt < 2; mt++)
        #pragma unroll
        for (int nt = 0; nt < 4; nt++) {
            acc[mt][nt][0] += blv[nt].x; acc[mt][nt][1] += blv[nt].y;
            acc[mt][nt][2] += blv[nt].x; acc[mt][nt][3] += blv[nt].y;
        }
    int wn = w >> 2;
    #pragma unroll
    for (int mt = 0; mt < 2; mt++) {
        #pragma unroll
        for (int h = 0; h < 2; h++) {
            float s = 0.f, q = 0.f;
            #pragma unroll
            for (int nt = 0; nt < 4; nt++) {
                float v0 = acc[mt][nt][h * 2], v1 = acc[mt][nt][h * 2 + 1];
                s += v0 + v1;
                q += v0 * v0 + v1 * v1;
            }
            s += __shfl_xor_sync(0xffffffffu, s, 1);
            q += __shfl_xor_sync(0xffffffffu, q, 1);
            s += __shfl_xor_sync(0xffffffffu, s, 2);
            q += __shfl_xor_sync(0xffffffffu, q, 2);
            if ((lane & 3) == 0) {
                int r = mblk + mt * 16 + h * 8 + (lane >> 2);
                sRed[r * 2 + wn] = make_float2(s, q);
            }
        }
    }
    __syncthreads();
    float2 gv[4], bbv[4];
    #pragma unroll
    for (int nt = 0; nt < 4; nt++) {
        gv[nt] = *(const float2*)(lng + c0 + nt * 8);
        bbv[nt] = *(const float2*)(lnb + c0 + nt * 8);
    }
    #pragma unroll
    for (int mt = 0; mt < 2; mt++) {
        #pragma unroll
        for (int h = 0; h < 2; h++) {
            int r = mblk + mt * 16 + h * 8 + (lane >> 2);
            float2 p0 = sRed[r * 2 + 0], p1 = sRed[r * 2 + 1];
            float S = p0.x + p1.x, Q = p0.y + p1.y;
            float mean = S * (1.f / 64.f);
            float var = Q * (1.f / 64.f) - mean * mean;
            float rstd = rsqrtf(var + 1e-5f);
            int grow = base + r;
            if (grow < NN) {
                float* orow = hout + (long)grow * 64;
                const float* rrow = hin + (long)grow * 64;
                #pragma unroll
                for (int nt = 0; nt < 4; nt++) {
                    float2 res = *(const float2*)(rrow + c0 + nt * 8);
                    float v0 = acc[mt][nt][h * 2], v1 = acc[mt][nt][h * 2 + 1];
                    float2 o;
                    o.x = silu_f((v0 - mean) * rstd * gv[nt].x + bbv[nt].x + res.x);
                    o.y = silu_f((v1 - mean) * rstd * gv[nt].y + bbv[nt].y + res.y);
                    *(float2*)(orow + c0 + nt * 8) = o;
                }
            }
        }
    }
}

// ---------------- node MLP via mma.sync bf16 hi/lo: silu(h@W1+b1) -> LN -> @W2+b2 ----
// Persistent blocks; tile M=32 (100000/32=3125 exact). Weights in SMEM hi/lo.
// G1: M32 N256 K64 (8 warps of 32x32). G2: M32 N64 K256 (2m x 4n warps of 16x16).
#define W1H_OFF 0
#define W1L_OFF 36864
#define W2H_OFF 73728
#define W2L_OFF 107520
#define AH_OFF  141312
#define AL_OFF  145920
#define TH_OFF  150528
#define TL_OFF  167424
#define RED_OFF 184320
#define MLP2_SMEM 186368
__global__ __launch_bounds__(256) void mlp_mma_kernel(
    const float* __restrict__ hin, const float* __restrict__ W1, const float* __restrict__ b1,
    const float* __restrict__ gg, const float* __restrict__ bn,
    const float* __restrict__ W2, const float* __restrict__ b2, float* __restrict__ hout) {
    extern __shared__ char smem[];
    uint32_t sb = smem_u32(smem);
    float2* sRed = (float2*)(smem + RED_OFF);  // [32 rows][8 warps]
    int tid = threadIdx.x;
    int w = tid >> 5, lane = tid & 31;

    // ---- stage weights (once per block): W1^T (n=256,k=64) and W2^T (n=64,k=256)
    {
        int n = tid;  // 0..255
        uint32_t dh = sb + W1H_OFF + n * 144;
        uint32_t dl = sb + W1L_OFF + n * 144;
        #pragma unroll
        for (int it = 0; it < 16; it++) {
            int k = it * 4;
            float4 f;
            f.x = __ldg(W1 + (k + 0) * 256 + n);
            f.y = __ldg(W1 + (k + 1) * 256 + n);
            f.z = __ldg(W1 + (k + 2) * 256 + n);
            f.w = __ldg(W1 + (k + 3) * 256 + n);
            uint32_t h01, h23, l01, l23;
            split_pack(f, h01, h23, l01, l23);
            asm volatile("st.shared.v2.u32 [%0], {%1,%2};" :: "r"(dh + k * 2), "r"(h01), "r"(h23));
            asm volatile("st.shared.v2.u32 [%0], {%1,%2};" :: "r"(dl + k * 2), "r"(l01), "r"(l23));
        }
    }
    {
        int n = tid & 63, kq = tid >> 6;
        uint32_t dh = sb + W2H_OFF + n * 528 + kq * 128;
        uint32_t dl = sb + W2L_OFF + n * 528 + kq * 128;
        #pragma unroll
        for (int it = 0; it < 16; it++) {
            int k = kq * 64 + it * 4;
            float4 f;
            f.x = __ldg(W2 + (k + 0) * 64 + n);
            f.y = __ldg(W2 + (k + 1) * 64 + n);
            f.z = __ldg(W2 + (k + 2) * 64 + n);
            f.w = __ldg(W2 + (k + 3) * 64 + n);
            uint32_t h01, h23, l01, l23;
            split_pack(f, h01, h23, l01, l23);
            asm volatile("st.shared.v2.u32 [%0], {%1,%2};" :: "r"(dh + it * 8), "r"(h01), "r"(h23));
            asm volatile("st.shared.v2.u32 [%0], {%1,%2};" :: "r"(dl + it * 8), "r"(l01), "r"(l23));
        }
    }

    // epilogue/LN constants for G1 (cols owned by this warp) and G2
    int c0w = w * 32 + (lane & 3) * 2;  // G1 col base
    float2 b1v[4], gv[4], bnv[4];
    #pragma unroll
    for (int nt = 0; nt < 4; nt++) {
        b1v[nt] = *(const float2*)(b1 + c0w + nt * 8);
        gv[nt] = *(const float2*)(gg + c0w + nt * 8);
        bnv[nt] = *(const float2*)(bn + c0w + nt * 8);
    }
    int wm2 = w & 1, wn2 = w >> 1;
    int mblk2 = wm2 * 16, nblk2 = wn2 * 16;
    int c02 = nblk2 + (lane & 3) * 2;
    float2 b2v[2];
    b2v[0] = *(const float2*)(b2 + c02);
    b2v[1] = *(const float2*)(b2 + c02 + 8);

    uint32_t aRel = (uint32_t)((lane & 15) * 144 + ((lane >> 4) & 1) * 16);
    uint32_t bRel = (uint32_t)((w * 32 + ((lane >> 4) & 1) * 8 + (lane & 7)) * 144 +
                               ((lane >> 3) & 1) * 16);
    uint32_t aRel2 = (uint32_t)((mblk2 + (lane & 15)) * 528 + ((lane >> 4) & 1) * 16);
    uint32_t bRel2 = (uint32_t)((nblk2 + ((lane >> 4) & 1) * 8 + (lane & 7)) * 528 +
                                ((lane >> 3) & 1) * 16);

    const int NT = NN / 32;  // 3125 exact
    for (int t = blockIdx.x; t < NT; t += gridDim.x) {
        __syncthreads();
        int base = t * 32;
        // ---- A = h rows, hi/lo
        {
            int row = tid >> 3, ci = tid & 7;
            const float* hr = hin + (long)(base + row) * 64 + ci * 8;
            float4 f0 = *(const float4*)hr;
            float4 f1 = *(const float4*)(hr + 4);
            uint32_t h01, h23, l01, l23;
            split_pack(f0, h01, h23, l01, l23);
            uint32_t d = row * 144 + ci * 16;
            asm volatile("st.shared.v2.u32 [%0], {%1,%2};" :: "r"(sb + AH_OFF + d), "r"(h01), "r"(h23));
            asm volatile("st.shared.v2.u32 [%0], {%1,%2};" :: "r"(sb + AL_OFF + d), "r"(l01), "r"(l23));
            split_pack(f1, h01, h23, l01, l23);
            asm volatile("st.shared.v2.u32 [%0], {%1,%2};" :: "r"(sb + AH_OFF + d + 8), "r"(h01), "r"(h23));
            asm volatile("st.shared.v2.u32 [%0], {%1,%2};" :: "r"(sb + AL_OFF + d + 8), "r"(l01), "r"(l23));
        }
        __syncthreads();

        // ---- G1: M32 N256 K64; warp covers 32 rows x 32 cols
        float acc[2][4][4];
        #pragma unroll
        for (int a = 0; a < 2; a++)
            #pragma unroll
            for (int b = 0; b < 4; b++)
                #pragma unroll
                for (int c = 0; c < 4; c++) acc[a][b][c] = 0.f;
        #pragma unroll
        for (int s = 0; s < 4; s++) {
            uint32_t ko = (uint32_t)(s * 32);
            uint32_t ah0[4], ah1[4], al0[4], al1[4];
            ldsm4(ah0, sb + AH_OFF + aRel + ko);
            ldsm4(ah1, sb + AH_OFF + aRel + 2304 + ko);
            ldsm4(al0, sb + AL_OFF + aRel + ko);
            ldsm4(al1, sb + AL_OFF + aRel + 2304 + ko);
            uint32_t bh0[4], bh1[4], bL0[4], bL1[4];
            ldsm4(bh0, sb + W1H_OFF + bRel + ko);
            ldsm4(bh1, sb + W1H_OFF + bRel + 2304 + ko);
            ldsm4(bL0, sb + W1L_OFF + bRel + ko);
            ldsm4(bL1, sb + W1L_OFF + bRel + 2304 + ko);
            #pragma unroll
            for (int nt = 0; nt < 4; nt++) {
                uint32_t bhx0 = (nt < 2) ? bh0[(nt & 1) * 2] : bh1[(nt & 1) * 2];
                uint32_t bhx1 = (nt < 2) ? bh0[(nt & 1) * 2 + 1] : bh1[(nt & 1) * 2 + 1];
                uint32_t blx0 = (nt < 2) ? bL0[(nt & 1) * 2] : bL1[(nt & 1) * 2];
                uint32_t blx1 = (nt < 2) ? bL0[(nt & 1) * 2 + 1] : bL1[(nt & 1) * 2 + 1];
                mma16816(acc[0][nt], ah0, bhx0, bhx1);
                mma16816(acc[0][nt], ah0, blx0, blx1);
                mma16816(acc[0][nt], al0, bhx0, bhx1);
                mma16816(acc[1][nt], ah1, bhx0, bhx1);
                mma16816(acc[1][nt], ah1, blx0, blx1);
                mma16816(acc[1][nt], al1, bhx0, bhx1);
            }
        }
        // bias + silu; LN partials across warp's 32 cols
        #pragma unroll
        for (int mt = 0; mt < 2; mt++) {
            #pragma unroll
            for (int nt = 0; nt < 4; nt++) {
                acc[mt][nt][0] = silu_f(acc[mt][nt][0] + b1v[nt].x);
                acc[mt][nt][1] = silu_f(acc[mt][nt][1] + b1v[nt].y);
                acc[mt][nt][2] = silu_f(acc[mt][nt][2] + b1v[nt].x);
                acc[mt][nt][3] = silu_f(acc[mt][nt][3] + b1v[nt].y);
            }
        }
        #pragma unroll
        for (int mt = 0; mt < 2; mt++) {
            #pragma unroll
            for (int h = 0; h < 2; h++) {
                float s = 0.f, q = 0.f;
                #pragma unroll
                for (int nt = 0; nt < 4; nt++) {
                    float v0 = acc[mt][nt][h * 2], v1 = acc[mt][nt][h * 2 + 1];
                    s += v0 + v1;
                    q += v0 * v0 + v1 * v1;
                }
                s += __shfl_xor_sync(0xffffffffu, s, 1);
                q += __shfl_xor_sync(0xffffffffu, q, 1);
                s += __shfl_xor_sync(0xffffffffu, s, 2);
                q += __shfl_xor_sync(0xffffffffu, q, 2);
                if ((lane & 3) == 0) {
                    int r = mt * 16 + h * 8 + (lane >> 2);
                    sRed[r * 8 + w] = make_float2(s, q);
                }
            }
        }
        __syncthreads();
        // LN normalize + split to T (hi/lo)
        #pragma unroll
        for (int mt = 0; mt < 2; mt++) {
            #pragma unroll
            for (int h = 0; h < 2; h++) {
                int r = mt * 16 + h * 8 + (lane >> 2);
                float S = 0.f, Q = 0.f;
                #pragma unroll
                for (int ww = 0; ww < 8; ww++) {
                    float2 p = sRed[r * 8 + ww];
                    S += p.x; Q += p.y;
                }
                float mean = S * (1.f / 256.f);
                float var = Q * (1.f / 256.f) - mean * mean;
                float rstd = rsqrtf(var + 1e-5f);
                #pragma unroll
                for (int nt = 0; nt < 4; nt++) {
                    float n0 = (acc[mt][nt][h * 2] - mean) * rstd * gv[nt].x + bnv[nt].x;
                    float n1 = (acc[mt][nt][h * 2 + 1] - mean) * rstd * gv[nt].y + bnv[nt].y;
                    uint32_t h01, l01;
                    split_pack2(n0, n1, h01, l01);
                    uint32_t d = (uint32_t)(r * 528 + (c0w + nt * 8) * 2);
                    asm volatile("st.shared.b32 [%0], %1;" :: "r"(sb + TH_OFF + d), "r"(h01));
                    asm volatile("st.shared.b32 [%0], %1;" :: "r"(sb + TL_OFF + d), "r"(l01));
                }
            }
        }
        __syncthreads();

        // ---- G2: M32 N64 K256; warp covers 16 rows x 16 cols
        float acc2[2][4];
        #pragma unroll
        for (int a = 0; a < 2; a++)
            #pragma unroll
            for (int c = 0; c < 4; c++) acc2[a][c] = 0.f;
        #pragma unroll
        for (int s = 0; s < 16; s++) {
            uint32_t ko = (uint32_t)(s * 32);
            uint32_t ah[4], al[4], bh[4], bL[4];
            ldsm4(ah, sb + TH_OFF + aRel2 + ko);
            ldsm4(al, sb + TL_OFF + aRel2 + ko);
            ldsm4(bh, sb + W2H_OFF + bRel2 + ko);
            ldsm4(bL, sb + W2L_OFF + bRel2 + ko);
            #pragma unroll
            for (int nt = 0; nt < 2; nt++) {
                uint32_t bhx0 = bh[nt * 2], bhx1 = bh[nt * 2 + 1];
                uint32_t blx0 = bL[nt * 2], blx1 = bL[nt * 2 + 1];
                mma16816(acc2[nt], ah, bhx0, bhx1);
                mma16816(acc2[nt], ah, blx0, blx1);
                mma16816(acc2[nt], al, bhx0, bhx1);
            }
        }
        #pragma unroll
        for (int nt = 0; nt < 2; nt++) {
            #pragma unroll
            for (int h = 0; h < 2; h++) {
                int r = mblk2 + h * 8 + (lane >> 2);
                int col = c02 + nt * 8;
                float2 o;
                o.x = acc2[nt][h * 2] + b2v[nt].x;
                o.y = acc2[nt][h * 2 + 1] + b2v[nt].y;
                *(float2*)(hout + (long)(base + r) * 64 + col) = o;
            }
        }
    }
}

// ---------------- graph pooling: mean | max | sum | root ----------------
__global__ __launch_bounds__(256) void pool_kernel(const float* __restrict__ h,
                                                   const float* __restrict__ x,
                                                   const int* __restrict__ ptr,
                                                   float* __restrict__ o) {
    int g = blockIdx.x;
    int start = ptr[g], end = ptr[g + 1];
    int tid = threadIdx.x;
    int rl = tid >> 6, d = tid & 63;
    float sm = 0.f, mx = -INFINITY;
    for (int r = start + rl; r < end; r += 4) {
        float v = h[(long)r * 64 + d];
        sm += v;
        mx = fmaxf(mx, v);
    }
    __shared__ float sS[4][64], sM[4][64];
    sS[rl][d] = sm; sM[rl][d] = mx;
    __syncthreads();
    if (tid < 64) {
        float s = sS[0][tid] + sS[1][tid] + sS[2][tid] + sS[3][tid];
        float m = fmaxf(fmaxf(sM[0][tid], sM[1][tid]), fmaxf(sM[2][tid], sM[3][tid]));
        int cnt = end - start;
        float mean = s / (float)(cnt > 0 ? cnt : 1);
        if (m == -INFINITY) m = 0.f;
        o[g * 196 + tid] = mean;
        o[g * 196 + 64 + tid] = m;
        o[g * 196 + 128 + tid] = s;
    }
    if (tid < 4) o[g * 196 + 192 + tid] = x[(long)start * 4 + tid];
}

// ---------------- readout: silu(o@W1+b1) -> LN -> @W2+b2 ----------------
__global__ __launch_bounds__(256) void readout_kernel(
    const float* __restrict__ o, const float* __restrict__ W1, const float* __restrict__ b1,
    const float* __restrict__ gg, const float* __restrict__ bn,
    const float* __restrict__ W2, const float* __restrict__ b2, float* __restrict__ out) {
    int g = blockIdx.x;
    int tid = threadIdx.x;
    __shared__ float so[196];
    __shared__ float red[256];
    __shared__ float ws[8][2];
    __shared__ float stats[2];
    if (tid < 196) so[tid] = o[g * 196 + tid];
    __syncthreads();
    float acc = __ldg(b1 + tid);
    #pragma unroll 4
    for (int k = 0; k < 196; k++) acc += so[k] * __ldg(W1 + k * 256 + tid);
    float s = silu_f(acc);
    float ls = s, lq = s * s;
    #pragma unroll
    for (int m2 = 1; m2 < 32; m2 <<= 1) {
        ls += __shfl_xor_sync(0xffffffffu, ls, m2);
        lq += __shfl_xor_sync(0xffffffffu, lq, m2);
    }
    int w = tid >> 5;
    if ((tid & 31) == 0) { ws[w][0] = ls; ws[w][1] = lq; }
    __syncthreads();
    if (tid == 0) {
        float S = 0.f, Q = 0.f;
        for (int i = 0; i < 8; i++) { S += ws[i][0]; Q += ws[i][1]; }
        stats[0] = S; stats[1] = Q;
    }
    __syncthreads();
    float mean = stats[0] * (1.f / 256.f);
    float var = stats[1] * (1.f / 256.f) - mean * mean;
    float rstd = rsqrtf(var + 1e-5f);
    float n = (s - mean) * rstd * __ldg(gg + tid) + __ldg(bn + tid);
    float4 w2 = *(const float4*)(W2 + tid * 4);
    float p[4] = {n * w2.x, n * w2.y, n * w2.z, n * w2.w};
    for (int j = 0; j < 4; j++) {
        red[tid] = p[j];
        __syncthreads();
        for (int st = 128; st > 0; st >>= 1) {
            if (tid < st) red[tid] += red[tid + st];
            __syncthreads();
        }
        if (tid == 0) out[g * 4 + j] = red[0] + __ldg(b2 + j);
        __syncthreads();
    }
}

// ---------------- launch ----------------
extern "C" void kernel_launch(void* const* d_in, const int* in_sizes, int n_in,
                              void* d_out, int out_size) {
    const float* x      = (const float*)d_in[0];
    const int*   ei     = (const int*)d_in[1];
    const int*   ptr    = (const int*)d_in[3];
    const float* Wl0    = (const float*)d_in[4];
    const float* bl0    = (const float*)d_in[5];
    const float* Wr0    = (const float*)d_in[6];
    const float* Wl     = (const float*)d_in[7];
    const float* bl     = (const float*)d_in[8];
    const float* Wr     = (const float*)d_in[9];
    const float* Wres   = (const float*)d_in[10];
    const float* bres   = (const float*)d_in[11];
    const float* ln_g   = (const float*)d_in[12];
    const float* ln_b   = (const float*)d_in[13];
    const float* mlp_W1 = (const float*)d_in[14];
    const float* mlp_b1 = (const float*)d_in[15];
    const float* mlp_g  = (const float*)d_in[16];
    const float* mlp_bn = (const float*)d_in[17];
    const float* mlp_W2 = (const float*)d_in[18];
    const float* mlp_b2 = (const float*)d_in[19];
    const float* ro_W1  = (const float*)d_in[20];
    const float* ro_b1  = (const float*)d_in[21];
    const float* ro_g   = (const float*)d_in[22];
    const float* ro_bn  = (const float*)d_in[23];
    const float* ro_W2  = (const float*)d_in[24];
    const float* ro_b2  = (const float*)d_in[25];
    float* out = (float*)d_out;

    void* p;
    cudaGetSymbolAddress(&p, g_deg);    int* deg = (int*)p;
    cudaGetSymbolAddress(&p, g_incl);   int* incl = (int*)p;
    cudaGetSymbolAddress(&p, g_rowptr); int* rowptr = (int*)p;
    cudaGetSymbolAddress(&p, g_cur);    int* cur = (int*)p;
    cudaGetSymbolAddress(&p, g_bsums);  int* bsums = (int*)p;
    cudaGetSymbolAddress(&p, g_csr);    int* csr = (int*)p;
    cudaGetSymbolAddress(&p, g_hA);     float* hA = (float*)p;
    cudaGetSymbolAddress(&p, g_hB);     float* hB = (float*)p;
    cudaGetSymbolAddress(&p, g_agg);    float* agg = (float*)p;
    cudaGetSymbolAddress(&p, g_obuf);   float* obuf = (float*)p;

    cudaFuncSetAttribute(sage_mma_kernel, cudaFuncAttributeMaxDynamicSharedMemorySize, MMA_SMEM);
    cudaFuncSetAttribute(mlp_mma_kernel, cudaFuncAttributeMaxDynamicSharedMemorySize, MLP2_SMEM);

    zero_deg_kernel<<<(NN + 255) / 256, 256>>>(deg);
    hist_kernel<<<(NE + 255) / 256, 256>>>(ei, deg);
    scan1_kernel<<<(NN + 1023) / 1024, 1024>>>(deg, incl, bsums);
    scan2_kernel<<<1, 128>>>(bsums, (NN + 1023) / 1024);
    scan3_kernel<<<(NN + 255) / 256, 256>>>(incl, deg, bsums, rowptr, cur);
    scatter_kernel<<<(NE + 255) / 256, 256>>>(ei, cur, csr);

    layer0_kernel<<<(NN + 3) / 4, 256>>>(x, rowptr, csr, Wl0, bl0, Wr0, Wres, bres,
                                         ln_g, ln_b, hA);

    const float* hin = hA;
    float* hout = hB;
    const int NTILE = (NN + 127) / 128;  // 782
    for (int i = 0; i < 3; i++) {
        agg_kernel<<<(NN + 3) / 4, 256>>>(hin, rowptr, csr, agg);
        sage_mma_kernel<<<NTILE, 256, MMA_SMEM>>>(agg, hin, Wl + i * 128 * 64, bl + i * 64,
                                                  Wr + i * 64 * 64, ln_g + (i + 1) * 64,
                                                  ln_b + (i + 1) * 64, hout);
        const float* tmp = hin;
        hin = hout;
        hout = (float*)tmp;
    }
    // hin == hB (final sage output), hout == hA
    mlp_mma_kernel<<<148, 256, MLP2_SMEM>>>(hin, mlp_W1, mlp_b1, mlp_g, mlp_bn,
                                            mlp_W2, mlp_b2, hout);
    pool_kernel<<<NG, 256>>>(hout, x, ptr, obuf);
    readout_kernel<<<NG, 256>>>(obuf, ro_W1, ro_b1, ro_g, ro_bn, ro_W2, ro_b2, out);
}